// round 2
// baseline (speedup 1.0000x reference)
#include <cuda_runtime.h>
#include <cstdint>
#include <math.h>

#define NROWS 32768
#define DIN   768
#define DOUT  768
#define NW    48
#define NH    16
#define LN_EPSF 1e-5f

#define BM 128
#define BN 128
#define BK 16
#define KTOT (DIN + NW)      // 816
#define NKT  (KTOT / BK)     // 51
#define SKEW 4

// Scratch (allocation-free rule: static __device__ arrays)
__device__ float g_wav[(size_t)NROWS * NW];
__device__ float g_h[(size_t)NROWS * DOUT];

__device__ __forceinline__ unsigned f2tf32(float f) {
    unsigned r;
    asm("cvt.rna.tf32.f32 %0, %1;" : "=r"(r) : "f"(f));
    return r;
}

// ---------------------------------------------------------------------------
// Kernel 1: wi = x @ Wp^T + bp ; s = (wi - t)/scale ; wav = gelu(basis(s))
// warp handles 4 rows; x rows in registers; Wp streamed via L1 (147KB resident)
// ---------------------------------------------------------------------------
__global__ __launch_bounds__(256) void k_wavelet(
    const float* __restrict__ x, const float* __restrict__ Wp,
    const float* __restrict__ bp, const float* __restrict__ scales,
    const float* __restrict__ trans)
{
    const int lane = threadIdx.x & 31;
    const int warp = threadIdx.x >> 5;
    const int row0 = (blockIdx.x * 8 + warp) * 4;

    float4 xr[4][6];
#pragma unroll
    for (int r = 0; r < 4; ++r) {
        const float4* xp = reinterpret_cast<const float4*>(x + (size_t)(row0 + r) * DIN);
#pragma unroll
        for (int i = 0; i < 6; ++i) xr[r][i] = xp[i * 32 + lane];
    }

    float kv[4][2];
#pragma unroll 1
    for (int j = 0; j < NW; ++j) {
        const float4* wp = reinterpret_cast<const float4*>(Wp + (size_t)j * DIN);
        float a0 = 0.f, a1 = 0.f, a2 = 0.f, a3 = 0.f;
#pragma unroll
        for (int i = 0; i < 6; ++i) {
            float4 w = __ldg(wp + i * 32 + lane);
            a0 += xr[0][i].x * w.x + xr[0][i].y * w.y + xr[0][i].z * w.z + xr[0][i].w * w.w;
            a1 += xr[1][i].x * w.x + xr[1][i].y * w.y + xr[1][i].z * w.z + xr[1][i].w * w.w;
            a2 += xr[2][i].x * w.x + xr[2][i].y * w.y + xr[2][i].z * w.z + xr[2][i].w * w.w;
            a3 += xr[3][i].x * w.x + xr[3][i].y * w.y + xr[3][i].z * w.z + xr[3][i].w * w.w;
        }
#pragma unroll
        for (int off = 16; off > 0; off >>= 1) {
            a0 += __shfl_xor_sync(0xffffffffu, a0, off);
            a1 += __shfl_xor_sync(0xffffffffu, a1, off);
            a2 += __shfl_xor_sync(0xffffffffu, a2, off);
            a3 += __shfl_xor_sync(0xffffffffu, a3, off);
        }
        if ((j & 31) == lane) {
            const int slot = j >> 5;
            kv[0][slot] = a0; kv[1][slot] = a1; kv[2][slot] = a2; kv[3][slot] = a3;
        }
    }

#pragma unroll
    for (int r = 0; r < 4; ++r) {
#pragma unroll
        for (int slot = 0; slot < 2; ++slot) {
            const int j = lane + slot * 32;
            if (j < NW) {
                const float wi = kv[r][slot] + bp[j];
                const float s = (wi - trans[j]) / scales[j];
                float wv;
                if (j < NH) {
                    wv = (s >= 0.f && s < 0.5f) ? 1.f
                       : ((s >= 0.5f && s < 1.f) ? -1.f : 0.f);
                } else if (j < 2 * NH) {
                    wv = (1.f - s * s) * expf(-0.5f * s * s);
                } else {
                    wv = cosf(5.0f * s) * expf(-0.5f * s * s);
                }
                const float g = 0.5f * wv * (1.f + erff(wv * 0.7071067811865475f));
                g_wav[(size_t)(row0 + r) * NW + j] = g;
            }
        }
    }
}

// ---------------------------------------------------------------------------
// Kernel 2: h = [x | wav] @ [W | Wc]^T + (b + bc)   (TF32 mma.sync GEMM)
// BM=128, BN=128, BK=16, 256 threads (8 warps as 2x4, warp tile 64x32)
// ---------------------------------------------------------------------------
__global__ __launch_bounds__(256) void k_gemm(
    const float* __restrict__ x, const float* __restrict__ W,
    const float* __restrict__ b, const float* __restrict__ Wc,
    const float* __restrict__ bc)
{
    __shared__ __align__(16) unsigned As[BM][BK + SKEW];
    __shared__ __align__(16) unsigned Bs[BN][BK + SKEW];
    __shared__ float bsum[BN];

    const int tid  = threadIdx.x;
    const int lane = tid & 31;
    const int warp = tid >> 5;
    const int wm = warp >> 2;          // 0..1  -> 64 rows
    const int wn = warp & 3;           // 0..3  -> 32 cols
    const int rowBase = blockIdx.y * BM;
    const int colBase = blockIdx.x * BN;

    if (tid < BN) bsum[tid] = b[colBase + tid] + bc[colBase + tid];

    const int lrow = tid >> 2;         // 0..63
    const int lq   = tid & 3;          // 0..3  (which float4 of the 16-float k row)

    float acc[4][4][4];
#pragma unroll
    for (int i = 0; i < 4; ++i)
#pragma unroll
        for (int jn = 0; jn < 4; ++jn)
#pragma unroll
            for (int c = 0; c < 4; ++c) acc[i][jn][c] = 0.f;

    // prefetch tile kt=0 (k0 = 0 < DIN)
    float4 pa0 = *reinterpret_cast<const float4*>(x + (size_t)(rowBase + lrow) * DIN + lq * 4);
    float4 pa1 = *reinterpret_cast<const float4*>(x + (size_t)(rowBase + lrow + 64) * DIN + lq * 4);
    float4 pb0 = *reinterpret_cast<const float4*>(W + (size_t)(colBase + lrow) * DIN + lq * 4);
    float4 pb1 = *reinterpret_cast<const float4*>(W + (size_t)(colBase + lrow + 64) * DIN + lq * 4);

    const int r0 = lane >> 2;
    const int kq = lane & 3;

    for (int kt = 0; kt < NKT; ++kt) {
        // store prefetched tile to smem (with RNA tf32 rounding)
        {
            uint4 u;
            u.x = f2tf32(pa0.x); u.y = f2tf32(pa0.y); u.z = f2tf32(pa0.z); u.w = f2tf32(pa0.w);
            *reinterpret_cast<uint4*>(&As[lrow][lq * 4]) = u;
            u.x = f2tf32(pa1.x); u.y = f2tf32(pa1.y); u.z = f2tf32(pa1.z); u.w = f2tf32(pa1.w);
            *reinterpret_cast<uint4*>(&As[lrow + 64][lq * 4]) = u;
            u.x = f2tf32(pb0.x); u.y = f2tf32(pb0.y); u.z = f2tf32(pb0.z); u.w = f2tf32(pb0.w);
            *reinterpret_cast<uint4*>(&Bs[lrow][lq * 4]) = u;
            u.x = f2tf32(pb1.x); u.y = f2tf32(pb1.y); u.z = f2tf32(pb1.z); u.w = f2tf32(pb1.w);
            *reinterpret_cast<uint4*>(&Bs[lrow + 64][lq * 4]) = u;
        }
        __syncthreads();

        // prefetch next tile while computing
        if (kt + 1 < NKT) {
            const int k0 = (kt + 1) * BK;
            if (k0 < DIN) {
                pa0 = *reinterpret_cast<const float4*>(x + (size_t)(rowBase + lrow) * DIN + k0 + lq * 4);
                pa1 = *reinterpret_cast<const float4*>(x + (size_t)(rowBase + lrow + 64) * DIN + k0 + lq * 4);
                pb0 = *reinterpret_cast<const float4*>(W + (size_t)(colBase + lrow) * DIN + k0 + lq * 4);
                pb1 = *reinterpret_cast<const float4*>(W + (size_t)(colBase + lrow + 64) * DIN + k0 + lq * 4);
            } else {
                const int kk = k0 - DIN;
                pa0 = *reinterpret_cast<const float4*>(g_wav + (size_t)(rowBase + lrow) * NW + kk + lq * 4);
                pa1 = *reinterpret_cast<const float4*>(g_wav + (size_t)(rowBase + lrow + 64) * NW + kk + lq * 4);
                pb0 = *reinterpret_cast<const float4*>(Wc + (size_t)(colBase + lrow) * NW + kk + lq * 4);
                pb1 = *reinterpret_cast<const float4*>(Wc + (size_t)(colBase + lrow + 64) * NW + kk + lq * 4);
            }
        }

#pragma unroll
        for (int ks = 0; ks < 2; ++ks) {
            const int ko = ks * 8;
            unsigned af[4][4];
            unsigned bf[4][2];
#pragma unroll
            for (int im = 0; im < 4; ++im) {
                const int m = wm * 64 + im * 16;
                af[im][0] = As[m + r0][ko + kq];
                af[im][1] = As[m + r0 + 8][ko + kq];
                af[im][2] = As[m + r0][ko + kq + 4];
                af[im][3] = As[m + r0 + 8][ko + kq + 4];
            }
#pragma unroll
            for (int in = 0; in < 4; ++in) {
                const int n = wn * 32 + in * 8;
                bf[in][0] = Bs[n + r0][ko + kq];
                bf[in][1] = Bs[n + r0][ko + kq + 4];
            }
#pragma unroll
            for (int im = 0; im < 4; ++im)
#pragma unroll
                for (int in = 0; in < 4; ++in) {
                    asm volatile(
                        "mma.sync.aligned.m16n8k8.row.col.f32.tf32.tf32.f32 "
                        "{%0,%1,%2,%3}, {%4,%5,%6,%7}, {%8,%9}, {%0,%1,%2,%3};"
                        : "+f"(acc[im][in][0]), "+f"(acc[im][in][1]),
                          "+f"(acc[im][in][2]), "+f"(acc[im][in][3])
                        : "r"(af[im][0]), "r"(af[im][1]), "r"(af[im][2]), "r"(af[im][3]),
                          "r"(bf[in][0]), "r"(bf[in][1]));
                }
        }
        __syncthreads();
    }

    // epilogue: + bias, write h
#pragma unroll
    for (int im = 0; im < 4; ++im) {
        const int r = rowBase + wm * 64 + im * 16 + r0;
#pragma unroll
        for (int in = 0; in < 4; ++in) {
            const int lc = wn * 32 + in * 8 + 2 * kq;
            const float b0 = bsum[lc], b1 = bsum[lc + 1];
            float2 v;
            v.x = acc[im][in][0] + b0; v.y = acc[im][in][1] + b1;
            *reinterpret_cast<float2*>(&g_h[(size_t)r * DOUT + colBase + lc]) = v;
            v.x = acc[im][in][2] + b0; v.y = acc[im][in][3] + b1;
            *reinterpret_cast<float2*>(&g_h[(size_t)(r + 8) * DOUT + colBase + lc]) = v;
        }
    }
}

// ---------------------------------------------------------------------------
// Kernel 3: LayerNorm over DOUT=768, warp per row
// ---------------------------------------------------------------------------
__global__ __launch_bounds__(256) void k_ln(
    const float* __restrict__ gamma, const float* __restrict__ beta,
    float* __restrict__ out)
{
    const int lane = threadIdx.x & 31;
    const int warp = threadIdx.x >> 5;
    const int row = blockIdx.x * 8 + warp;

    const float4* hp = reinterpret_cast<const float4*>(g_h + (size_t)row * DOUT);
    float4 v[6];
    float s = 0.f, sq = 0.f;
#pragma unroll
    for (int i = 0; i < 6; ++i) {
        const float4 t = hp[i * 32 + lane];
        v[i] = t;
        s  += t.x + t.y + t.z + t.w;
        sq += t.x * t.x + t.y * t.y + t.z * t.z + t.w * t.w;
    }
#pragma unroll
    for (int off = 16; off > 0; off >>= 1) {
        s  += __shfl_xor_sync(0xffffffffu, s,  off);
        sq += __shfl_xor_sync(0xffffffffu, sq, off);
    }
    const float mean = s * (1.f / DOUT);
    const float var  = sq * (1.f / DOUT) - mean * mean;
    const float rstd = rsqrtf(var + LN_EPSF);

    float4* op = reinterpret_cast<float4*>(out + (size_t)row * DOUT);
    const float4* gp = reinterpret_cast<const float4*>(gamma);
    const float4* bp = reinterpret_cast<const float4*>(beta);
#pragma unroll
    for (int i = 0; i < 6; ++i) {
        const int idx = i * 32 + lane;
        const float4 g = __ldg(gp + idx);
        const float4 bt = __ldg(bp + idx);
        float4 o;
        o.x = (v[i].x - mean) * rstd * g.x + bt.x;
        o.y = (v[i].y - mean) * rstd * g.y + bt.y;
        o.z = (v[i].z - mean) * rstd * g.z + bt.z;
        o.w = (v[i].w - mean) * rstd * g.w + bt.w;
        op[idx] = o;
    }
}

// ---------------------------------------------------------------------------
extern "C" void kernel_launch(void* const* d_in, const int* in_sizes, int n_in,
                              void* d_out, int out_size)
{
    const float* x     = (const float*)d_in[0];
    const float* W     = (const float*)d_in[1];
    const float* b     = (const float*)d_in[2];
    const float* Wp    = (const float*)d_in[3];
    const float* bp    = (const float*)d_in[4];
    const float* Wc    = (const float*)d_in[5];
    const float* bc    = (const float*)d_in[6];
    const float* scal  = (const float*)d_in[7];
    const float* trans = (const float*)d_in[8];
    const float* gamma = (const float*)d_in[9];
    const float* beta  = (const float*)d_in[10];
    float* out = (float*)d_out;

    k_wavelet<<<NROWS / 32, 256>>>(x, Wp, bp, scal, trans);

    dim3 g2(DOUT / BN, NROWS / BM);   // (6, 256)
    k_gemm<<<g2, 256>>>(x, W, b, Wc, bc);

    k_ln<<<NROWS / 8, 256>>>(gamma, beta, out);
}

// round 4
// speedup vs baseline: 1.4821x; 1.4821x over previous
#include <cuda_runtime.h>
#include <cstdint>
#include <math.h>

#define NROWS 32768
#define DIN   768
#define DOUT  768
#define NW    48
#define NH    16
#define LN_EPSF 1e-5f

// main GEMM tiling
#define BM 128
#define BN 128
#define BK 48
#define NKT 17                 // 16 x/W tiles + 1 wav/Wc tile
#define LDSS 52                // 48 + 4 skew (float stride; 20*r0 mod 32 hits all banks)
#define STAGES 3
#define STAGEF (2 * 128 * LDSS)          // floats per stage (A tile + B tile)
#define GSMEM  (STAGES * STAGEF * 4)     // 159744 bytes

// wavelet GEMM tiling (M=32768, N=48, K=768)
#define NKTW 16
#define WSTAGEF ((128 + 48) * LDSS)      // x tile + Wp tile, floats
#define WSMEM   (STAGES * WSTAGEF * 4)   // 109824 bytes

// Scratch (allocation-free rule: static __device__ arrays)
__device__ float g_wav[(size_t)NROWS * NW];
__device__ float g_h[(size_t)NROWS * DOUT];

__device__ __forceinline__ unsigned f2tf32(float f) {
    unsigned r;
    asm("cvt.rna.tf32.f32 %0, %1;" : "=r"(r) : "f"(f));
    return r;
}
// split v into tf32 hi + tf32 lo (3xTF32 trick; near-fp32 product accuracy)
__device__ __forceinline__ void tf32_split(float v, unsigned& hi, unsigned& lo) {
    hi = f2tf32(v);
    lo = f2tf32(v - __uint_as_float(hi));
}

__device__ __forceinline__ void cp16(float* smem_dst, const float* gmem_src) {
    unsigned s = (unsigned)__cvta_generic_to_shared(smem_dst);
    asm volatile("cp.async.cg.shared.global [%0], [%1], 16;\n" :: "r"(s), "l"(gmem_src));
}
__device__ __forceinline__ void cp_commit() {
    asm volatile("cp.async.commit_group;\n");
}
template <int N>
__device__ __forceinline__ void cp_wait() {
    asm volatile("cp.async.wait_group %0;\n" :: "n"(N));
}

__device__ __forceinline__ void mma_tf32(float* c, const unsigned* a, const unsigned* b) {
    asm volatile(
        "mma.sync.aligned.m16n8k8.row.col.f32.tf32.tf32.f32 "
        "{%0,%1,%2,%3}, {%4,%5,%6,%7}, {%8,%9}, {%0,%1,%2,%3};"
        : "+f"(c[0]), "+f"(c[1]), "+f"(c[2]), "+f"(c[3])
        : "r"(a[0]), "r"(a[1]), "r"(a[2]), "r"(a[3]), "r"(b[0]), "r"(b[1]));
}

// ---------------------------------------------------------------------------
// Kernel 1: wavelet path as a 3xTF32 tensor GEMM (near-fp32 wi — haar needs it).
// wi = x @ Wp^T ; s=(wi+bp-t)/scale ; wav = gelu(basis(s)) -> g_wav
// 256 thr = 8 warps, each warp 16 rows x 48 cols. cp.async 3-stage.
// ---------------------------------------------------------------------------
__global__ __launch_bounds__(256) void k_wavelet(
    const float* __restrict__ x, const float* __restrict__ Wp,
    const float* __restrict__ bp, const float* __restrict__ scales,
    const float* __restrict__ trans)
{
    extern __shared__ float sm[];
    const int tid  = threadIdx.x;
    const int lane = tid & 31;
    const int warp = tid >> 5;
    const int rowBase = blockIdx.x * 128;
    const int r0 = lane >> 2;
    const int kq = lane & 3;

    float acc[6][4];
#pragma unroll
    for (int nt = 0; nt < 6; ++nt)
#pragma unroll
        for (int c = 0; c < 4; ++c) acc[nt][c] = 0.f;

    // ---- load one (x, Wp) K-tile into stage st ----
    auto load_tile = [&](int st, int kt) {
        float* Xs = sm + st * WSTAGEF;
        float* Ws = Xs + 128 * LDSS;
#pragma unroll
        for (int i = 0; i < 6; ++i) {
            const int idx = i * 256 + tid;          // 0..1535
            const int row = idx / 12, c4 = idx % 12;
            cp16(&Xs[row * LDSS + c4 * 4],
                 x + (size_t)(rowBase + row) * DIN + kt * 48 + c4 * 4);
        }
#pragma unroll
        for (int i = 0; i < 3; ++i) {
            const int idx = i * 256 + tid;          // need 0..575
            if (idx < 576) {
                const int row = idx / 12, c4 = idx % 12;
                cp16(&Ws[row * LDSS + c4 * 4],
                     Wp + (size_t)row * DIN + kt * 48 + c4 * 4);
            }
        }
    };

#pragma unroll
    for (int s = 0; s < STAGES; ++s) { load_tile(s, s); cp_commit(); }

    for (int kt = 0; kt < NKTW; ++kt) {
        cp_wait<STAGES - 1>();
        __syncthreads();
        const int st = kt % STAGES;
        const float* Xs = sm + st * WSTAGEF;
        const float* Ws = Xs + 128 * LDSS;
        const int m = warp * 16;
#pragma unroll
        for (int ks = 0; ks < 6; ++ks) {
            const int ko = ks * 8;
            unsigned ah[4], al[4];
            tf32_split(Xs[(m + r0) * LDSS + ko + kq],          ah[0], al[0]);
            tf32_split(Xs[(m + r0 + 8) * LDSS + ko + kq],      ah[1], al[1]);
            tf32_split(Xs[(m + r0) * LDSS + ko + kq + 4],      ah[2], al[2]);
            tf32_split(Xs[(m + r0 + 8) * LDSS + ko + kq + 4],  ah[3], al[3]);
#pragma unroll
            for (int nt = 0; nt < 6; ++nt) {
                unsigned bh[2], bl[2];
                tf32_split(Ws[(nt * 8 + r0) * LDSS + ko + kq],     bh[0], bl[0]);
                tf32_split(Ws[(nt * 8 + r0) * LDSS + ko + kq + 4], bh[1], bl[1]);
                mma_tf32(acc[nt], ah, bl);   // hi*lo
                mma_tf32(acc[nt], al, bh);   // lo*hi
                mma_tf32(acc[nt], ah, bh);   // hi*hi
            }
        }
        __syncthreads();
        if (kt + STAGES < NKTW) load_tile(st, kt + STAGES);
        cp_commit();
    }

    // ---- epilogue: wavelet basis + exact GELU, compile-time family per nt ----
    const int rA = rowBase + warp * 16 + r0;
#pragma unroll
    for (int nt = 0; nt < 6; ++nt) {
        const int j0 = nt * 8 + 2 * kq;
        const float bp0 = __ldg(bp + j0),     bp1 = __ldg(bp + j0 + 1);
        const float t0  = __ldg(trans + j0),  t1  = __ldg(trans + j0 + 1);
        const float sc0 = __ldg(scales + j0), sc1 = __ldg(scales + j0 + 1);
#pragma unroll
        for (int half = 0; half < 2; ++half) {
            const int r = rA + half * 8;
            const float s0 = (acc[nt][half * 2 + 0] + bp0 - t0) / sc0;
            const float s1 = (acc[nt][half * 2 + 1] + bp1 - t1) / sc1;
            float w0, w1;
            if (nt < 2) {               // haar
                w0 = (s0 >= 0.f && s0 < 0.5f) ? 1.f : ((s0 >= 0.5f && s0 < 1.f) ? -1.f : 0.f);
                w1 = (s1 >= 0.f && s1 < 0.5f) ? 1.f : ((s1 >= 0.5f && s1 < 1.f) ? -1.f : 0.f);
            } else if (nt < 4) {        // mexican hat
                w0 = (1.f - s0 * s0) * expf(-0.5f * s0 * s0);
                w1 = (1.f - s1 * s1) * expf(-0.5f * s1 * s1);
            } else {                    // morlet
                w0 = cosf(5.0f * s0) * expf(-0.5f * s0 * s0);
                w1 = cosf(5.0f * s1) * expf(-0.5f * s1 * s1);
            }
            float2 o;
            o.x = 0.5f * w0 * (1.f + erff(w0 * 0.7071067811865475f));
            o.y = 0.5f * w1 * (1.f + erff(w1 * 0.7071067811865475f));
            *reinterpret_cast<float2*>(&g_wav[(size_t)r * NW + j0]) = o;
        }
    }
}

// ---------------------------------------------------------------------------
// Kernel 2: h = [x | wav] @ [W | Wc]^T + (b + bc)
// BK=48, cp.async 3-stage, 8 warps as 2x4 (warp tile 64x32), single TF32
// ---------------------------------------------------------------------------
__global__ __launch_bounds__(256) void k_gemm(
    const float* __restrict__ x, const float* __restrict__ W,
    const float* __restrict__ b, const float* __restrict__ Wc,
    const float* __restrict__ bc)
{
    extern __shared__ float sm[];
    __shared__ float bsum[BN];

    const int tid  = threadIdx.x;
    const int lane = tid & 31;
    const int warp = tid >> 5;
    const int wm = warp >> 2;
    const int wn = warp & 3;
    const int rowBase = blockIdx.y * BM;
    const int colBase = blockIdx.x * BN;
    const int r0 = lane >> 2;
    const int kq = lane & 3;

    if (tid < BN) bsum[tid] = b[colBase + tid] + bc[colBase + tid];

    float acc[4][4][4];
#pragma unroll
    for (int i = 0; i < 4; ++i)
#pragma unroll
        for (int jn = 0; jn < 4; ++jn)
#pragma unroll
            for (int c = 0; c < 4; ++c) acc[i][jn][c] = 0.f;

    auto load_tile = [&](int st, int kt) {
        float* As = sm + st * STAGEF;
        float* Bs = As + 128 * LDSS;
#pragma unroll
        for (int i = 0; i < 6; ++i) {
            const int idx = i * 256 + tid;
            const int row = idx / 12, c4 = idx % 12;
            const float* srcA = (kt < 16)
                ? x + (size_t)(rowBase + row) * DIN + kt * 48 + c4 * 4
                : g_wav + (size_t)(rowBase + row) * NW + c4 * 4;
            cp16(&As[row * LDSS + c4 * 4], srcA);
            const float* srcB = (kt < 16)
                ? W + (size_t)(colBase + row) * DIN + kt * 48 + c4 * 4
                : Wc + (size_t)(colBase + row) * NW + c4 * 4;
            cp16(&Bs[row * LDSS + c4 * 4], srcB);
        }
    };

#pragma unroll
    for (int s = 0; s < STAGES; ++s) { load_tile(s, s); cp_commit(); }

    for (int kt = 0; kt < NKT; ++kt) {
        cp_wait<STAGES - 1>();
        __syncthreads();
        const int st = kt % STAGES;
        const float* As = sm + st * STAGEF;
        const float* Bs = As + 128 * LDSS;
#pragma unroll
        for (int ks = 0; ks < 6; ++ks) {
            const int ko = ks * 8;
            unsigned af[4][4];
            unsigned bf[4][2];
#pragma unroll
            for (int im = 0; im < 4; ++im) {
                const int m = wm * 64 + im * 16;
                af[im][0] = f2tf32(As[(m + r0) * LDSS + ko + kq]);
                af[im][1] = f2tf32(As[(m + r0 + 8) * LDSS + ko + kq]);
                af[im][2] = f2tf32(As[(m + r0) * LDSS + ko + kq + 4]);
                af[im][3] = f2tf32(As[(m + r0 + 8) * LDSS + ko + kq + 4]);
            }
#pragma unroll
            for (int in = 0; in < 4; ++in) {
                const int n = wn * 32 + in * 8;
                bf[in][0] = f2tf32(Bs[(n + r0) * LDSS + ko + kq]);
                bf[in][1] = f2tf32(Bs[(n + r0) * LDSS + ko + kq + 4]);
            }
#pragma unroll
            for (int im = 0; im < 4; ++im)
#pragma unroll
                for (int in = 0; in < 4; ++in)
                    mma_tf32(acc[im][in], af[im], bf[in]);
        }
        __syncthreads();
        if (kt + STAGES < NKT) load_tile(st, kt + STAGES);
        cp_commit();
    }

    // epilogue: + bias, write h
#pragma unroll
    for (int im = 0; im < 4; ++im) {
        const int r = rowBase + wm * 64 + im * 16 + r0;
#pragma unroll
        for (int in = 0; in < 4; ++in) {
            const int lc = wn * 32 + in * 8 + 2 * kq;
            const float b0 = bsum[lc], b1 = bsum[lc + 1];
            float2 v;
            v.x = acc[im][in][0] + b0; v.y = acc[im][in][1] + b1;
            *reinterpret_cast<float2*>(&g_h[(size_t)r * DOUT + colBase + lc]) = v;
            v.x = acc[im][in][2] + b0; v.y = acc[im][in][3] + b1;
            *reinterpret_cast<float2*>(&g_h[(size_t)(r + 8) * DOUT + colBase + lc]) = v;
        }
    }
}

// ---------------------------------------------------------------------------
// Kernel 3: LayerNorm over DOUT=768, warp per row
// ---------------------------------------------------------------------------
__global__ __launch_bounds__(256) void k_ln(
    const float* __restrict__ gamma, const float* __restrict__ beta,
    float* __restrict__ out)
{
    const int lane = threadIdx.x & 31;
    const int warp = threadIdx.x >> 5;
    const int row = blockIdx.x * 8 + warp;

    const float4* hp = reinterpret_cast<const float4*>(g_h + (size_t)row * DOUT);
    float4 v[6];
    float s = 0.f, sq = 0.f;
#pragma unroll
    for (int i = 0; i < 6; ++i) {
        const float4 t = hp[i * 32 + lane];
        v[i] = t;
        s  += t.x + t.y + t.z + t.w;
        sq += t.x * t.x + t.y * t.y + t.z * t.z + t.w * t.w;
    }
#pragma unroll
    for (int off = 16; off > 0; off >>= 1) {
        s  += __shfl_xor_sync(0xffffffffu, s,  off);
        sq += __shfl_xor_sync(0xffffffffu, sq, off);
    }
    const float mean = s * (1.f / DOUT);
    const float var  = sq * (1.f / DOUT) - mean * mean;
    const float rstd = rsqrtf(var + LN_EPSF);

    float4* op = reinterpret_cast<float4*>(out + (size_t)row * DOUT);
    const float4* gp = reinterpret_cast<const float4*>(gamma);
    const float4* bp = reinterpret_cast<const float4*>(beta);
#pragma unroll
    for (int i = 0; i < 6; ++i) {
        const int idx = i * 32 + lane;
        const float4 g = __ldg(gp + idx);
        const float4 bt = __ldg(bp + idx);
        float4 o;
        o.x = (v[i].x - mean) * rstd * g.x + bt.x;
        o.y = (v[i].y - mean) * rstd * g.y + bt.y;
        o.z = (v[i].z - mean) * rstd * g.z + bt.z;
        o.w = (v[i].w - mean) * rstd * g.w + bt.w;
        op[idx] = o;
    }
}

// ---------------------------------------------------------------------------
extern "C" void kernel_launch(void* const* d_in, const int* in_sizes, int n_in,
                              void* d_out, int out_size)
{
    const float* x     = (const float*)d_in[0];
    const float* W     = (const float*)d_in[1];
    const float* b     = (const float*)d_in[2];
    const float* Wp    = (const float*)d_in[3];
    const float* bp    = (const float*)d_in[4];
    const float* Wc    = (const float*)d_in[5];
    const float* bc    = (const float*)d_in[6];
    const float* scal  = (const float*)d_in[7];
    const float* trans = (const float*)d_in[8];
    const float* gamma = (const float*)d_in[9];
    const float* beta  = (const float*)d_in[10];
    float* out = (float*)d_out;

    // >48KB dynamic smem opt-in (idempotent host-side config; capture-safe)
    cudaFuncSetAttribute(k_wavelet, cudaFuncAttributeMaxDynamicSharedMemorySize, WSMEM);
    cudaFuncSetAttribute(k_gemm,    cudaFuncAttributeMaxDynamicSharedMemorySize, GSMEM);

    k_wavelet<<<NROWS / 128, 256, WSMEM>>>(x, Wp, bp, scal, trans);

    dim3 g2(DOUT / BN, NROWS / BM);   // (6, 256)
    k_gemm<<<g2, 256, GSMEM>>>(x, W, b, Wc, bc);

    k_ln<<<NROWS / 8, 256>>>(gamma, beta, out);
}

// round 5
// speedup vs baseline: 1.5984x; 1.0785x over previous
#include <cuda_runtime.h>
#include <cstdint>
#include <math.h>

#define NROWS 32768
#define DIN   768
#define DOUT  768
#define NW    48
#define NH    16
#define LN_EPSF 1e-5f

// main GEMM tiling
#define BM 128
#define BN 128
#define BK 48
#define NKT 17                 // 16 x/W tiles + 1 wav/Wc tile
#define LDSS 52                // 48 + 4 skew (float stride; 20*r0 mod 32 hits all banks)
#define STAGES 2
#define STAGEF (2 * 128 * LDSS)          // floats per stage (A tile + B tile)
#define GSMEM  (STAGES * STAGEF * 4)     // 106496 bytes -> 2 CTAs/SM

// wavelet GEMM tiling (M=32768, N=48, K=768); B region holds Wp_hi(48)+Wp_lo(48)
#define NKTW 16
#define WSTAGEF ((128 + 96) * LDSS)      // x tile + split Wp tiles, floats
#define WSMEM   (STAGES * WSTAGEF * 4)   // 93184 bytes -> 2 CTAs/SM

// Scratch (allocation-free rule: static __device__ arrays)
__device__ float g_wav[(size_t)NROWS * NW];
__device__ float g_h[(size_t)NROWS * DOUT];
__device__ float g_wp_hi[(size_t)NW * DIN];
__device__ float g_wp_lo[(size_t)NW * DIN];

__device__ __forceinline__ unsigned f2tf32(float f) {
    unsigned r;
    asm("cvt.rna.tf32.f32 %0, %1;" : "=r"(r) : "f"(f));
    return r;
}
__device__ __forceinline__ void tf32_split(float v, unsigned& hi, unsigned& lo) {
    hi = f2tf32(v);
    lo = f2tf32(v - __uint_as_float(hi));
}

__device__ __forceinline__ void cp16(float* smem_dst, const float* gmem_src) {
    unsigned s = (unsigned)__cvta_generic_to_shared(smem_dst);
    asm volatile("cp.async.cg.shared.global [%0], [%1], 16;\n" :: "r"(s), "l"(gmem_src));
}
__device__ __forceinline__ void cp_commit() {
    asm volatile("cp.async.commit_group;\n");
}
template <int N>
__device__ __forceinline__ void cp_wait() {
    asm volatile("cp.async.wait_group %0;\n" :: "n"(N));
}

__device__ __forceinline__ void mma_tf32(float* c, const unsigned* a, const unsigned* b) {
    asm volatile(
        "mma.sync.aligned.m16n8k8.row.col.f32.tf32.tf32.f32 "
        "{%0,%1,%2,%3}, {%4,%5,%6,%7}, {%8,%9}, {%0,%1,%2,%3};"
        : "+f"(c[0]), "+f"(c[1]), "+f"(c[2]), "+f"(c[3])
        : "r"(a[0]), "r"(a[1]), "r"(a[2]), "r"(a[3]), "r"(b[0]), "r"(b[1]));
}

// ---------------------------------------------------------------------------
// Kernel 0: pre-split Wp into tf32 hi/lo (done per call; deterministic)
// ---------------------------------------------------------------------------
__global__ void k_split(const float* __restrict__ Wp) {
    const int i = blockIdx.x * 256 + threadIdx.x;
    if (i < NW * DIN) {
        const float v = Wp[i];
        const float hi = __uint_as_float(f2tf32(v));
        g_wp_hi[i] = hi;
        g_wp_lo[i] = __uint_as_float(f2tf32(v - hi));
    }
}

// ---------------------------------------------------------------------------
// Kernel 1: wavelet path as a 3xTF32 tensor GEMM (near-fp32 wi — haar needs it).
// B operand pre-split (raw LDS, no cvt); A split in-register (once per warp).
// ---------------------------------------------------------------------------
__global__ __launch_bounds__(256, 2) void k_wavelet(
    const float* __restrict__ x,
    const float* __restrict__ bp, const float* __restrict__ scales,
    const float* __restrict__ trans)
{
    extern __shared__ float sm[];
    const int tid  = threadIdx.x;
    const int lane = tid & 31;
    const int warp = tid >> 5;
    const int rowBase = blockIdx.x * 128;
    const int r0 = lane >> 2;
    const int kq = lane & 3;

    float acc[6][4];
#pragma unroll
    for (int nt = 0; nt < 6; ++nt)
#pragma unroll
        for (int c = 0; c < 4; ++c) acc[nt][c] = 0.f;

    // ---- load one (x, Wp_hi, Wp_lo) K-tile into stage st ----
    auto load_tile = [&](int st, int kt) {
        float* Xs = sm + st * WSTAGEF;
        float* Ws = Xs + 128 * LDSS;       // rows 0..47 hi, 48..95 lo
#pragma unroll
        for (int i = 0; i < 6; ++i) {
            const int idx = i * 256 + tid;          // 0..1535
            const int row = idx / 12, c4 = idx % 12;
            cp16(&Xs[row * LDSS + c4 * 4],
                 x + (size_t)(rowBase + row) * DIN + kt * 48 + c4 * 4);
        }
#pragma unroll
        for (int i = 0; i < 5; ++i) {
            const int idx = i * 256 + tid;          // need 0..1151
            if (idx < 1152) {
                const int row = idx / 12, c4 = idx % 12;   // row 0..95
                const float* src = (row < 48)
                    ? g_wp_hi + (size_t)row * DIN + kt * 48 + c4 * 4
                    : g_wp_lo + (size_t)(row - 48) * DIN + kt * 48 + c4 * 4;
                cp16(&Ws[row * LDSS + c4 * 4], src);
            }
        }
    };

#pragma unroll
    for (int s = 0; s < STAGES; ++s) { load_tile(s, s); cp_commit(); }

    for (int kt = 0; kt < NKTW; ++kt) {
        cp_wait<STAGES - 1>();
        __syncthreads();
        const int st = kt % STAGES;
        const float* Xs = sm + st * WSTAGEF;
        const float* Ws = Xs + 128 * LDSS;
        const int m = warp * 16;
#pragma unroll
        for (int ks = 0; ks < 6; ++ks) {
            const int ko = ks * 8;
            unsigned ah[4], al[4];
            tf32_split(Xs[(m + r0) * LDSS + ko + kq],          ah[0], al[0]);
            tf32_split(Xs[(m + r0 + 8) * LDSS + ko + kq],      ah[1], al[1]);
            tf32_split(Xs[(m + r0) * LDSS + ko + kq + 4],      ah[2], al[2]);
            tf32_split(Xs[(m + r0 + 8) * LDSS + ko + kq + 4],  ah[3], al[3]);
#pragma unroll
            for (int nt = 0; nt < 6; ++nt) {
                unsigned bh[2], bl[2];
                bh[0] = __float_as_uint(Ws[(nt * 8 + r0) * LDSS + ko + kq]);
                bh[1] = __float_as_uint(Ws[(nt * 8 + r0) * LDSS + ko + kq + 4]);
                bl[0] = __float_as_uint(Ws[(48 + nt * 8 + r0) * LDSS + ko + kq]);
                bl[1] = __float_as_uint(Ws[(48 + nt * 8 + r0) * LDSS + ko + kq + 4]);
                mma_tf32(acc[nt], ah, bl);   // hi*lo
                mma_tf32(acc[nt], al, bh);   // lo*hi
                mma_tf32(acc[nt], ah, bh);   // hi*hi
            }
        }
        __syncthreads();
        if (kt + STAGES < NKTW) load_tile(st, kt + STAGES);
        cp_commit();
    }

    // ---- epilogue: wavelet basis + exact GELU, compile-time family per nt ----
    const int rA = rowBase + warp * 16 + r0;
#pragma unroll
    for (int nt = 0; nt < 6; ++nt) {
        const int j0 = nt * 8 + 2 * kq;
        const float bp0 = __ldg(bp + j0),     bp1 = __ldg(bp + j0 + 1);
        const float t0  = __ldg(trans + j0),  t1  = __ldg(trans + j0 + 1);
        const float sc0 = __ldg(scales + j0), sc1 = __ldg(scales + j0 + 1);
#pragma unroll
        for (int half = 0; half < 2; ++half) {
            const int r = rA + half * 8;
            const float s0 = (acc[nt][half * 2 + 0] + bp0 - t0) / sc0;
            const float s1 = (acc[nt][half * 2 + 1] + bp1 - t1) / sc1;
            float w0, w1;
            if (nt < 2) {               // haar
                w0 = (s0 >= 0.f && s0 < 0.5f) ? 1.f : ((s0 >= 0.5f && s0 < 1.f) ? -1.f : 0.f);
                w1 = (s1 >= 0.f && s1 < 0.5f) ? 1.f : ((s1 >= 0.5f && s1 < 1.f) ? -1.f : 0.f);
            } else if (nt < 4) {        // mexican hat
                w0 = (1.f - s0 * s0) * expf(-0.5f * s0 * s0);
                w1 = (1.f - s1 * s1) * expf(-0.5f * s1 * s1);
            } else {                    // morlet
                w0 = cosf(5.0f * s0) * expf(-0.5f * s0 * s0);
                w1 = cosf(5.0f * s1) * expf(-0.5f * s1 * s1);
            }
            float2 o;
            o.x = 0.5f * w0 * (1.f + erff(w0 * 0.7071067811865475f));
            o.y = 0.5f * w1 * (1.f + erff(w1 * 0.7071067811865475f));
            *reinterpret_cast<float2*>(&g_wav[(size_t)r * NW + j0]) = o;
        }
    }
}

// ---------------------------------------------------------------------------
// Kernel 2: h = [x | wav] @ [W | Wc]^T + (b + bc)
// BK=48, cp.async 2-stage, 2 CTAs/SM, 8 warps as 2x4 (warp tile 64x32)
// ---------------------------------------------------------------------------
__global__ __launch_bounds__(256, 2) void k_gemm(
    const float* __restrict__ x, const float* __restrict__ W,
    const float* __restrict__ b, const float* __restrict__ Wc,
    const float* __restrict__ bc)
{
    extern __shared__ float sm[];
    __shared__ float bsum[BN];

    const int tid  = threadIdx.x;
    const int lane = tid & 31;
    const int warp = tid >> 5;
    const int wm = warp >> 2;
    const int wn = warp & 3;
    const int rowBase = blockIdx.y * BM;
    const int colBase = blockIdx.x * BN;
    const int r0 = lane >> 2;
    const int kq = lane & 3;

    if (tid < BN) bsum[tid] = b[colBase + tid] + bc[colBase + tid];

    float acc[4][4][4];
#pragma unroll
    for (int i = 0; i < 4; ++i)
#pragma unroll
        for (int jn = 0; jn < 4; ++jn)
#pragma unroll
            for (int c = 0; c < 4; ++c) acc[i][jn][c] = 0.f;

    auto load_tile = [&](int st, int kt) {
        float* As = sm + st * STAGEF;
        float* Bs = As + 128 * LDSS;
#pragma unroll
        for (int i = 0; i < 6; ++i) {
            const int idx = i * 256 + tid;
            const int row = idx / 12, c4 = idx % 12;
            const float* srcA = (kt < 16)
                ? x + (size_t)(rowBase + row) * DIN + kt * 48 + c4 * 4
                : g_wav + (size_t)(rowBase + row) * NW + c4 * 4;
            cp16(&As[row * LDSS + c4 * 4], srcA);
            const float* srcB = (kt < 16)
                ? W + (size_t)(colBase + row) * DIN + kt * 48 + c4 * 4
                : Wc + (size_t)(colBase + row) * NW + c4 * 4;
            cp16(&Bs[row * LDSS + c4 * 4], srcB);
        }
    };

#pragma unroll
    for (int s = 0; s < STAGES; ++s) { load_tile(s, s); cp_commit(); }

    for (int kt = 0; kt < NKT; ++kt) {
        cp_wait<STAGES - 1>();
        __syncthreads();
        const int st = kt % STAGES;
        const float* As = sm + st * STAGEF;
        const float* Bs = As + 128 * LDSS;
#pragma unroll
        for (int ks = 0; ks < 6; ++ks) {
            const int ko = ks * 8;
            unsigned af[4][4];
            unsigned bf[4][2];
#pragma unroll
            for (int im = 0; im < 4; ++im) {
                const int m = wm * 64 + im * 16;
                af[im][0] = f2tf32(As[(m + r0) * LDSS + ko + kq]);
                af[im][1] = f2tf32(As[(m + r0 + 8) * LDSS + ko + kq]);
                af[im][2] = f2tf32(As[(m + r0) * LDSS + ko + kq + 4]);
                af[im][3] = f2tf32(As[(m + r0 + 8) * LDSS + ko + kq + 4]);
            }
#pragma unroll
            for (int in = 0; in < 4; ++in) {
                const int n = wn * 32 + in * 8;
                bf[in][0] = f2tf32(Bs[(n + r0) * LDSS + ko + kq]);
                bf[in][1] = f2tf32(Bs[(n + r0) * LDSS + ko + kq + 4]);
            }
#pragma unroll
            for (int im = 0; im < 4; ++im)
#pragma unroll
                for (int in = 0; in < 4; ++in)
                    mma_tf32(acc[im][in], af[im], bf[in]);
        }
        __syncthreads();
        if (kt + STAGES < NKT) load_tile(st, kt + STAGES);
        cp_commit();
    }

    // epilogue: + bias, write h
#pragma unroll
    for (int im = 0; im < 4; ++im) {
        const int r = rowBase + wm * 64 + im * 16 + r0;
#pragma unroll
        for (int in = 0; in < 4; ++in) {
            const int lc = wn * 32 + in * 8 + 2 * kq;
            const float b0 = bsum[lc], b1 = bsum[lc + 1];
            float2 v;
            v.x = acc[im][in][0] + b0; v.y = acc[im][in][1] + b1;
            *reinterpret_cast<float2*>(&g_h[(size_t)r * DOUT + colBase + lc]) = v;
            v.x = acc[im][in][2] + b0; v.y = acc[im][in][3] + b1;
            *reinterpret_cast<float2*>(&g_h[(size_t)(r + 8) * DOUT + colBase + lc]) = v;
        }
    }
}

// ---------------------------------------------------------------------------
// Kernel 3: LayerNorm over DOUT=768, warp per row
// ---------------------------------------------------------------------------
__global__ __launch_bounds__(256) void k_ln(
    const float* __restrict__ gamma, const float* __restrict__ beta,
    float* __restrict__ out)
{
    const int lane = threadIdx.x & 31;
    const int warp = threadIdx.x >> 5;
    const int row = blockIdx.x * 8 + warp;

    const float4* hp = reinterpret_cast<const float4*>(g_h + (size_t)row * DOUT);
    float4 v[6];
    float s = 0.f, sq = 0.f;
#pragma unroll
    for (int i = 0; i < 6; ++i) {
        const float4 t = hp[i * 32 + lane];
        v[i] = t;
        s  += t.x + t.y + t.z + t.w;
        sq += t.x * t.x + t.y * t.y + t.z * t.z + t.w * t.w;
    }
#pragma unroll
    for (int off = 16; off > 0; off >>= 1) {
        s  += __shfl_xor_sync(0xffffffffu, s,  off);
        sq += __shfl_xor_sync(0xffffffffu, sq, off);
    }
    const float mean = s * (1.f / DOUT);
    const float var  = sq * (1.f / DOUT) - mean * mean;
    const float rstd = rsqrtf(var + LN_EPSF);

    float4* op = reinterpret_cast<float4*>(out + (size_t)row * DOUT);
    const float4* gp = reinterpret_cast<const float4*>(gamma);
    const float4* bp = reinterpret_cast<const float4*>(beta);
#pragma unroll
    for (int i = 0; i < 6; ++i) {
        const int idx = i * 32 + lane;
        const float4 g = __ldg(gp + idx);
        const float4 bt = __ldg(bp + idx);
        float4 o;
        o.x = (v[i].x - mean) * rstd * g.x + bt.x;
        o.y = (v[i].y - mean) * rstd * g.y + bt.y;
        o.z = (v[i].z - mean) * rstd * g.z + bt.z;
        o.w = (v[i].w - mean) * rstd * g.w + bt.w;
        op[idx] = o;
    }
}

// ---------------------------------------------------------------------------
extern "C" void kernel_launch(void* const* d_in, const int* in_sizes, int n_in,
                              void* d_out, int out_size)
{
    const float* x     = (const float*)d_in[0];
    const float* W     = (const float*)d_in[1];
    const float* b     = (const float*)d_in[2];
    const float* Wp    = (const float*)d_in[3];
    const float* bp    = (const float*)d_in[4];
    const float* Wc    = (const float*)d_in[5];
    const float* bc    = (const float*)d_in[6];
    const float* scal  = (const float*)d_in[7];
    const float* trans = (const float*)d_in[8];
    const float* gamma = (const float*)d_in[9];
    const float* beta  = (const float*)d_in[10];
    float* out = (float*)d_out;

    // >48KB dynamic smem opt-in (idempotent host-side config; capture-safe)
    cudaFuncSetAttribute(k_wavelet, cudaFuncAttributeMaxDynamicSharedMemorySize, WSMEM);
    cudaFuncSetAttribute(k_gemm,    cudaFuncAttributeMaxDynamicSharedMemorySize, GSMEM);

    k_split<<<(NW * DIN + 255) / 256, 256>>>(Wp);

    k_wavelet<<<NROWS / 128, 256, WSMEM>>>(x, bp, scal, trans);

    dim3 g2(DOUT / BN, NROWS / BM);   // (6, 256)
    k_gemm<<<g2, 256, GSMEM>>>(x, W, b, Wc, bc);

    k_ln<<<NROWS / 8, 256>>>(gamma, beta, out);
}

// round 8
// speedup vs baseline: 2.6945x; 1.6858x over previous
#include <cuda_runtime.h>
#include <cstdint>
#include <math.h>

#define NROWS 32768
#define DIN   768
#define DOUT  768
#define NW    48
#define NH    16
#define NWP   64                 // padded wavelet width (stride of g_wav / g_wc_pad)
#define LN_EPSF 1e-5f

// ---------------- main GEMM tiling (shared by both bodies) ----------------
#define TC_BM 128
#define TC_BN 256
#define TC_NKT 26                // K-tiles of 32 floats (768+64 = 832)
#define TC_STAGES 4
#define A_BYTES (128 * 128)      // 16 KB
#define B_BYTES (256 * 128)      // 32 KB
#define STAGE_BYTES (A_BYTES + B_BYTES)            // 48 KB
#define MBAR_OFF  (TC_STAGES * STAGE_BYTES)        // 196608
#define TMEMP_OFF (MBAR_OFF + 6 * 8)
#define TC_SMEM   (TMEMP_OFF + 16)

// idesc: dtype=F32(1)@[4], atype=TF32(2)@[7], btype=TF32(2)@[10], N/8@[17], M/16@[24]
#define TC_IDESC ((1u << 4) | (2u << 7) | (2u << 10) | ((TC_BN / 8) << 17) | ((TC_BM / 16) << 24))

// SW128 K-major SMEM descriptor: LBO=1, SBO=64, version=1, layout=SW128(2)
#define DESC_BASE ((uint64_t(2) << 61) | (uint64_t(1) << 46) | (uint64_t(64) << 32) | (uint64_t(1) << 16))
#define SW128(o) ((o) ^ (((o) >> 3) & 0x70))

// fallback (mma.sync) layout inside the same smem budget
#define FB_BK  32
#define FB_LDS 36
#define FB_STAGEF ((128 + 256) * FB_LDS)   // floats per stage

// ---------------- wavelet GEMM tiling (mma.sync 3xTF32) ----------------
#define LDSS 52
#define WSTAGES 2
#define NKTW 16
#define WSTAGEF ((128 + 96) * LDSS)
#define WSMEM   (WSTAGES * WSTAGEF * 4)   // 93184 bytes

// Scratch (allocation-free rule: static __device__ arrays)
__device__ float g_wav[(size_t)NROWS * NWP];
__device__ float g_h[(size_t)NROWS * DOUT];
__device__ float g_wp_hi[(size_t)NW * DIN];
__device__ float g_wp_lo[(size_t)NW * DIN];
__device__ float g_wc_pad[(size_t)DOUT * NWP];

// ---------------- helpers ----------------
__device__ __forceinline__ unsigned f2tf32(float f) {
    unsigned r;
    asm("cvt.rna.tf32.f32 %0, %1;" : "=r"(r) : "f"(f));
    return r;
}
__device__ __forceinline__ void tf32_split(float v, unsigned& hi, unsigned& lo) {
    hi = f2tf32(v);
    lo = f2tf32(v - __uint_as_float(hi));
}
__device__ __forceinline__ unsigned smem_u32(const void* p) {
    return (unsigned)__cvta_generic_to_shared(p);
}
__device__ __forceinline__ void cp16(void* smem_dst, const float* gmem_src) {
    asm volatile("cp.async.cg.shared.global [%0], [%1], 16;\n"
                 :: "r"(smem_u32(smem_dst)), "l"(gmem_src));
}
__device__ __forceinline__ void cp_commit() {
    asm volatile("cp.async.commit_group;\n");
}
template <int N>
__device__ __forceinline__ void cp_wait() {
    asm volatile("cp.async.wait_group %0;\n" :: "n"(N));
}
__device__ __forceinline__ void mma_tf32(float* c, const unsigned* a, const unsigned* b) {
    asm volatile(
        "mma.sync.aligned.m16n8k8.row.col.f32.tf32.tf32.f32 "
        "{%0,%1,%2,%3}, {%4,%5,%6,%7}, {%8,%9}, {%0,%1,%2,%3};"
        : "+f"(c[0]), "+f"(c[1]), "+f"(c[2]), "+f"(c[3])
        : "r"(a[0]), "r"(a[1]), "r"(a[2]), "r"(a[3]), "r"(b[0]), "r"(b[1]));
}

// ---------------------------------------------------------------------------
// Kernel 0a: pre-split Wp into tf32 hi/lo
// ---------------------------------------------------------------------------
__global__ void k_split(const float* __restrict__ Wp) {
    const int i = blockIdx.x * 256 + threadIdx.x;
    if (i < NW * DIN) {
        const float v = Wp[i];
        const float hi = __uint_as_float(f2tf32(v));
        g_wp_hi[i] = hi;
        g_wp_lo[i] = __uint_as_float(f2tf32(v - hi));
    }
}

// ---------------------------------------------------------------------------
// Kernel 0b: repack Wc [DOUT,48] -> g_wc_pad [DOUT,64] zero-padded
// ---------------------------------------------------------------------------
__global__ void k_wcpad(const float* __restrict__ Wc) {
    const int i = blockIdx.x * 256 + threadIdx.x;
    if (i < DOUT * NWP) {
        const int n = i >> 6, k = i & 63;
        g_wc_pad[i] = (k < NW) ? Wc[n * NW + k] : 0.f;
    }
}

// ---------------------------------------------------------------------------
// Kernel 1: wavelet path, 3xTF32 mma.sync GEMM; output stride 64, pad zeroed
// ---------------------------------------------------------------------------
__global__ __launch_bounds__(256, 2) void k_wavelet(
    const float* __restrict__ x,
    const float* __restrict__ bp, const float* __restrict__ scales,
    const float* __restrict__ trans)
{
    extern __shared__ float sm[];
    const int tid  = threadIdx.x;
    const int lane = tid & 31;
    const int warp = tid >> 5;
    const int rowBase = blockIdx.x * 128;
    const int r0 = lane >> 2;
    const int kq = lane & 3;

    float acc[6][4];
#pragma unroll
    for (int nt = 0; nt < 6; ++nt)
#pragma unroll
        for (int c = 0; c < 4; ++c) acc[nt][c] = 0.f;

    auto load_tile = [&](int st, int kt) {
        float* Xs = sm + st * WSTAGEF;
        float* Ws = Xs + 128 * LDSS;
#pragma unroll
        for (int i = 0; i < 6; ++i) {
            const int idx = i * 256 + tid;
            const int row = idx / 12, c4 = idx % 12;
            cp16(&Xs[row * LDSS + c4 * 4],
                 x + (size_t)(rowBase + row) * DIN + kt * 48 + c4 * 4);
        }
#pragma unroll
        for (int i = 0; i < 5; ++i) {
            const int idx = i * 256 + tid;
            if (idx < 1152) {
                const int row = idx / 12, c4 = idx % 12;
                const float* src = (row < 48)
                    ? g_wp_hi + (size_t)row * DIN + kt * 48 + c4 * 4
                    : g_wp_lo + (size_t)(row - 48) * DIN + kt * 48 + c4 * 4;
                cp16(&Ws[row * LDSS + c4 * 4], src);
            }
        }
    };

#pragma unroll
    for (int s = 0; s < WSTAGES; ++s) { load_tile(s, s); cp_commit(); }

    for (int kt = 0; kt < NKTW; ++kt) {
        cp_wait<WSTAGES - 1>();
        __syncthreads();
        const int st = kt % WSTAGES;
        const float* Xs = sm + st * WSTAGEF;
        const float* Ws = Xs + 128 * LDSS;
        const int m = warp * 16;
#pragma unroll
        for (int ks = 0; ks < 6; ++ks) {
            const int ko = ks * 8;
            unsigned ah[4], al[4];
            tf32_split(Xs[(m + r0) * LDSS + ko + kq],          ah[0], al[0]);
            tf32_split(Xs[(m + r0 + 8) * LDSS + ko + kq],      ah[1], al[1]);
            tf32_split(Xs[(m + r0) * LDSS + ko + kq + 4],      ah[2], al[2]);
            tf32_split(Xs[(m + r0 + 8) * LDSS + ko + kq + 4],  ah[3], al[3]);
#pragma unroll
            for (int nt = 0; nt < 6; ++nt) {
                unsigned bh[2], bl[2];
                bh[0] = __float_as_uint(Ws[(nt * 8 + r0) * LDSS + ko + kq]);
                bh[1] = __float_as_uint(Ws[(nt * 8 + r0) * LDSS + ko + kq + 4]);
                bl[0] = __float_as_uint(Ws[(48 + nt * 8 + r0) * LDSS + ko + kq]);
                bl[1] = __float_as_uint(Ws[(48 + nt * 8 + r0) * LDSS + ko + kq + 4]);
                mma_tf32(acc[nt], ah, bl);
                mma_tf32(acc[nt], al, bh);
                mma_tf32(acc[nt], ah, bh);
            }
        }
        __syncthreads();
        if (kt + WSTAGES < NKTW) load_tile(st, kt + WSTAGES);
        cp_commit();
    }

    // zero the pad columns 48..63 for this block's 128 rows
#pragma unroll
    for (int i = 0; i < 8; ++i) {
        const int idx = i * 256 + tid;          // 0..2047
        const int row = idx >> 4, col = 48 + (idx & 15);
        g_wav[(size_t)(rowBase + row) * NWP + col] = 0.f;
    }

    const int rA = rowBase + warp * 16 + r0;
#pragma unroll
    for (int nt = 0; nt < 6; ++nt) {
        const int j0 = nt * 8 + 2 * kq;
        const float bp0 = __ldg(bp + j0),     bp1 = __ldg(bp + j0 + 1);
        const float t0  = __ldg(trans + j0),  t1  = __ldg(trans + j0 + 1);
        const float sc0 = __ldg(scales + j0), sc1 = __ldg(scales + j0 + 1);
#pragma unroll
        for (int half = 0; half < 2; ++half) {
            const int r = rA + half * 8;
            const float s0 = (acc[nt][half * 2 + 0] + bp0 - t0) / sc0;
            const float s1 = (acc[nt][half * 2 + 1] + bp1 - t1) / sc1;
            float w0, w1;
            if (nt < 2) {               // haar
                w0 = (s0 >= 0.f && s0 < 0.5f) ? 1.f : ((s0 >= 0.5f && s0 < 1.f) ? -1.f : 0.f);
                w1 = (s1 >= 0.f && s1 < 0.5f) ? 1.f : ((s1 >= 0.5f && s1 < 1.f) ? -1.f : 0.f);
            } else if (nt < 4) {        // mexican hat
                w0 = (1.f - s0 * s0) * expf(-0.5f * s0 * s0);
                w1 = (1.f - s1 * s1) * expf(-0.5f * s1 * s1);
            } else {                    // morlet
                w0 = cosf(5.0f * s0) * expf(-0.5f * s0 * s0);
                w1 = cosf(5.0f * s1) * expf(-0.5f * s1 * s1);
            }
            float2 o;
            o.x = 0.5f * w0 * (1.f + erff(w0 * 0.7071067811865475f));
            o.y = 0.5f * w1 * (1.f + erff(w1 * 0.7071067811865475f));
            *reinterpret_cast<float2*>(&g_wav[(size_t)r * NWP + j0]) = o;
        }
    }
}

// ---------------------------------------------------------------------------
// Kernel 2: main GEMM. Body selected at compile time per target:
//   sm_103a pass -> tcgen05 kind::tf32 SS pipeline
//   sm_103 pass  -> mma.sync TF32 fallback (same launch config)
// ---------------------------------------------------------------------------
__global__ __launch_bounds__(256, 1) void k_gemm_tc(
    const float* __restrict__ x, const float* __restrict__ W,
    const float* __restrict__ b, const float* __restrict__ bc)
{
#if defined(__CUDA_ARCH__) && defined(__CUDA_ARCH_FEAT_SM103_ALL)
    // ==================== tcgen05 body ====================
    extern __shared__ char smc[];
    const unsigned smem_base = smem_u32(smc);
    const int tid  = threadIdx.x;
    const int lane = tid & 31;
    const int warp = tid >> 5;
    const int rowBase = blockIdx.y * TC_BM;
    const int colBase = blockIdx.x * TC_BN;

    if (warp == 0) {
        asm volatile("tcgen05.alloc.cta_group::1.sync.aligned.shared::cta.b32 [%0], %1;"
                     :: "r"(smem_base + TMEMP_OFF), "r"(256u) : "memory");
    }
    if (tid == 0) {
#pragma unroll
        for (int s = 0; s < 5; ++s)
            asm volatile("mbarrier.init.shared.b64 [%0], 1;"
                         :: "r"(smem_base + MBAR_OFF + s * 8) : "memory");
    }
    __syncthreads();
    unsigned tmem_base;
    asm volatile("ld.shared.b32 %0, [%1];" : "=r"(tmem_base) : "r"(smem_base + TMEMP_OFF));

    auto load_tile = [&](int st, int kt) {
        char* At = smc + st * STAGE_BYTES;
        char* Bt = At + A_BYTES;
        if (kt < 24) {
            const float* xs = x + (size_t)rowBase * DIN + kt * 32;
            const float* ws = W + (size_t)colBase * DIN + kt * 32;
#pragma unroll
            for (int i = 0; i < 4; ++i) {
                const int idx = i * 256 + tid;
                const int row = idx >> 3, c = idx & 7;
                cp16(At + SW128(row * 128 + c * 16), xs + (size_t)row * DIN + c * 4);
            }
#pragma unroll
            for (int i = 0; i < 8; ++i) {
                const int idx = i * 256 + tid;
                const int row = idx >> 3, c = idx & 7;
                cp16(Bt + SW128(row * 128 + c * 16), ws + (size_t)row * DIN + c * 4);
            }
        } else {
            const int kk = (kt - 24) * 32;
            const float* xs = g_wav + (size_t)rowBase * NWP + kk;
            const float* ws = g_wc_pad + (size_t)colBase * NWP + kk;
#pragma unroll
            for (int i = 0; i < 4; ++i) {
                const int idx = i * 256 + tid;
                const int row = idx >> 3, c = idx & 7;
                cp16(At + SW128(row * 128 + c * 16), xs + (size_t)row * NWP + c * 4);
            }
#pragma unroll
            for (int i = 0; i < 8; ++i) {
                const int idx = i * 256 + tid;
                const int row = idx >> 3, c = idx & 7;
                cp16(Bt + SW128(row * 128 + c * 16), ws + (size_t)row * NWP + c * 4);
            }
        }
    };

#pragma unroll
    for (int s = 0; s < TC_STAGES; ++s) { load_tile(s, s); cp_commit(); }

    unsigned ph[TC_STAGES] = {0, 0, 0, 0};

    auto mbar_wait = [&](unsigned mbar, unsigned parity) {
        asm volatile(
            "{\n\t.reg .pred P;\n\t"
            "W_%=: mbarrier.try_wait.parity.shared.b64 P, [%0], %1;\n\t"
            "@P bra D_%=;\n\t"
            "bra W_%=;\n\t"
            "D_%=:\n\t}"
            :: "r"(mbar), "r"(parity) : "memory");
    };

    for (int kt = 0; kt < TC_NKT; ++kt) {
        cp_wait<TC_STAGES - 1>();
        __syncthreads();
        asm volatile("fence.proxy.async.shared::cta;" ::: "memory");
        const int st = kt % TC_STAGES;

        if (tid == 0) {
            const uint64_t adesc = DESC_BASE |
                (uint64_t)(((smem_base + st * STAGE_BYTES) >> 4) & 0x3FFF);
            const uint64_t bdesc = DESC_BASE |
                (uint64_t)(((smem_base + st * STAGE_BYTES + A_BYTES) >> 4) & 0x3FFF);
#pragma unroll
            for (int step = 0; step < 4; ++step) {
                const unsigned en = (kt > 0 || step > 0) ? 1u : 0u;
                asm volatile(
                    "{\n\t.reg .pred p;\n\t"
                    "setp.ne.u32 p, %4, 0;\n\t"
                    "tcgen05.mma.cta_group::1.kind::tf32 [%0], %1, %2, %3, {%5, %5, %5, %5}, p;\n\t}"
                    :: "r"(tmem_base), "l"(adesc + step * 2), "l"(bdesc + step * 2),
                       "r"((unsigned)TC_IDESC), "r"(en), "r"(0u)
                    : "memory");
            }
            asm volatile(
                "tcgen05.commit.cta_group::1.mbarrier::arrive::one.shared::cluster.b64 [%0];"
                :: "r"(smem_base + MBAR_OFF + st * 8) : "memory");
        }

        if (kt + TC_STAGES < TC_NKT) {
            mbar_wait(smem_base + MBAR_OFF + st * 8, ph[st]);
            ph[st] ^= 1;
            load_tile(st, kt + TC_STAGES);
        }
        cp_commit();
    }

    if (tid == 0)
        asm volatile(
            "tcgen05.commit.cta_group::1.mbarrier::arrive::one.shared::cluster.b64 [%0];"
            :: "r"(smem_base + MBAR_OFF + 4 * 8) : "memory");
    mbar_wait(smem_base + MBAR_OFF + 4 * 8, 0);
    asm volatile("tcgen05.fence::after_thread_sync;" ::: "memory");

    const int sub = warp & 3;
    const int colBlk = (warp >> 2) * 128;
    const int row = rowBase + sub * 32 + lane;
#pragma unroll
    for (int chunk = 0; chunk < 4; ++chunk) {
        unsigned r[32];
        asm volatile(
            "tcgen05.ld.sync.aligned.32x32b.x32.b32 "
            "{%0, %1, %2, %3, %4, %5, %6, %7, %8, %9, %10, %11, %12, %13, %14, %15, "
            " %16, %17, %18, %19, %20, %21, %22, %23, %24, %25, %26, %27, %28, %29, %30, %31}, [%32];"
            : "=r"(r[0]), "=r"(r[1]), "=r"(r[2]), "=r"(r[3]), "=r"(r[4]), "=r"(r[5]),
              "=r"(r[6]), "=r"(r[7]), "=r"(r[8]), "=r"(r[9]), "=r"(r[10]), "=r"(r[11]),
              "=r"(r[12]), "=r"(r[13]), "=r"(r[14]), "=r"(r[15]), "=r"(r[16]), "=r"(r[17]),
              "=r"(r[18]), "=r"(r[19]), "=r"(r[20]), "=r"(r[21]), "=r"(r[22]), "=r"(r[23]),
              "=r"(r[24]), "=r"(r[25]), "=r"(r[26]), "=r"(r[27]), "=r"(r[28]), "=r"(r[29]),
              "=r"(r[30]), "=r"(r[31])
            : "r"(tmem_base + colBlk + chunk * 32));
        asm volatile("tcgen05.wait::ld.sync.aligned;" ::: "memory");
        const int c0 = colBase + colBlk + chunk * 32;
#pragma unroll
        for (int q = 0; q < 8; ++q) {
            const int cc = c0 + q * 4;
            float4 v;
            v.x = __uint_as_float(r[q * 4 + 0]) + __ldg(b + cc)     + __ldg(bc + cc);
            v.y = __uint_as_float(r[q * 4 + 1]) + __ldg(b + cc + 1) + __ldg(bc + cc + 1);
            v.z = __uint_as_float(r[q * 4 + 2]) + __ldg(b + cc + 2) + __ldg(bc + cc + 2);
            v.w = __uint_as_float(r[q * 4 + 3]) + __ldg(b + cc + 3) + __ldg(bc + cc + 3);
            *reinterpret_cast<float4*>(&g_h[(size_t)row * DOUT + cc]) = v;
        }
    }

    __syncthreads();
    if (warp == 0) {
        asm volatile("tcgen05.dealloc.cta_group::1.sync.aligned.b32 %0, %1;"
                     :: "r"(tmem_base), "r"(256u));
    }
#else
    // ==================== mma.sync fallback body ====================
    extern __shared__ float smf[];
    const int tid  = threadIdx.x;
    const int lane = tid & 31;
    const int warp = tid >> 5;
    const int wm = warp >> 2;            // 0..1 -> 64 rows
    const int wn = warp & 3;             // 0..3 -> 64 cols
    const int rowBase = blockIdx.y * TC_BM;
    const int colBase = blockIdx.x * TC_BN;
    const int r0 = lane >> 2;
    const int kq = lane & 3;

    float acc[4][8][4];
#pragma unroll
    for (int i = 0; i < 4; ++i)
#pragma unroll
        for (int j = 0; j < 8; ++j)
#pragma unroll
            for (int c = 0; c < 4; ++c) acc[i][j][c] = 0.f;

    auto load_tile = [&](int st, int kt) {
        float* As = smf + st * FB_STAGEF;
        float* Bs = As + 128 * FB_LDS;
        const bool main = (kt < 24);
        const int kk = main ? kt * 32 : (kt - 24) * 32;
        const float* aB = main ? x : g_wav;
        const float* bB = main ? W : g_wc_pad;
        const int aStride = main ? DIN : NWP;
#pragma unroll
        for (int i = 0; i < 4; ++i) {
            const int idx = i * 256 + tid;           // A: 1024 float4
            const int row = idx >> 3, c = idx & 7;
            cp16(&As[row * FB_LDS + c * 4],
                 aB + (size_t)(rowBase + row) * aStride + kk + c * 4);
        }
#pragma unroll
        for (int i = 0; i < 8; ++i) {
            const int idx = i * 256 + tid;           // B: 2048 float4
            const int row = idx >> 3, c = idx & 7;
            cp16(&Bs[row * FB_LDS + c * 4],
                 bB + (size_t)(colBase + row) * aStride + kk + c * 4);
        }
    };

#pragma unroll
    for (int s = 0; s < 2; ++s) { load_tile(s, s); cp_commit(); }

    for (int kt = 0; kt < TC_NKT; ++kt) {
        cp_wait<1>();
        __syncthreads();
        const int st = kt & 1;
        const float* As = smf + st * FB_STAGEF;
        const float* Bs = As + 128 * FB_LDS;
#pragma unroll
        for (int ks = 0; ks < 4; ++ks) {
            const int ko = ks * 8;
            unsigned af[4][4];
            unsigned bf[8][2];
#pragma unroll
            for (int im = 0; im < 4; ++im) {
                const int m = wm * 64 + im * 16;
                af[im][0] = f2tf32(As[(m + r0) * FB_LDS + ko + kq]);
                af[im][1] = f2tf32(As[(m + r0 + 8) * FB_LDS + ko + kq]);
                af[im][2] = f2tf32(As[(m + r0) * FB_LDS + ko + kq + 4]);
                af[im][3] = f2tf32(As[(m + r0 + 8) * FB_LDS + ko + kq + 4]);
            }
#pragma unroll
            for (int in = 0; in < 8; ++in) {
                const int n = wn * 64 + in * 8;
                bf[in][0] = f2tf32(Bs[(n + r0) * FB_LDS + ko + kq]);
                bf[in][1] = f2tf32(Bs[(n + r0) * FB_LDS + ko + kq + 4]);
            }
#pragma unroll
            for (int im = 0; im < 4; ++im)
#pragma unroll
                for (int in = 0; in < 8; ++in)
                    mma_tf32(acc[im][in], af[im], bf[in]);
        }
        __syncthreads();
        if (kt + 2 < TC_NKT) load_tile(st, kt + 2);
        cp_commit();
    }

#pragma unroll
    for (int im = 0; im < 4; ++im) {
        const int r = rowBase + wm * 64 + im * 16 + r0;
#pragma unroll
        for (int in = 0; in < 8; ++in) {
            const int cc = colBase + wn * 64 + in * 8 + 2 * kq;
            const float b0 = __ldg(b + cc) + __ldg(bc + cc);
            const float b1 = __ldg(b + cc + 1) + __ldg(bc + cc + 1);
            float2 v;
            v.x = acc[im][in][0] + b0; v.y = acc[im][in][1] + b1;
            *reinterpret_cast<float2*>(&g_h[(size_t)r * DOUT + cc]) = v;
            v.x = acc[im][in][2] + b0; v.y = acc[im][in][3] + b1;
            *reinterpret_cast<float2*>(&g_h[(size_t)(r + 8) * DOUT + cc]) = v;
        }
    }
#endif
}

// ---------------------------------------------------------------------------
// Kernel 3: LayerNorm over DOUT=768, warp per row
// ---------------------------------------------------------------------------
__global__ __launch_bounds__(256) void k_ln(
    const float* __restrict__ gamma, const float* __restrict__ beta,
    float* __restrict__ out)
{
    const int lane = threadIdx.x & 31;
    const int warp = threadIdx.x >> 5;
    const int row = blockIdx.x * 8 + warp;

    const float4* hp = reinterpret_cast<const float4*>(g_h + (size_t)row * DOUT);
    float4 v[6];
    float s = 0.f, sq = 0.f;
#pragma unroll
    for (int i = 0; i < 6; ++i) {
        const float4 t = hp[i * 32 + lane];
        v[i] = t;
        s  += t.x + t.y + t.z + t.w;
        sq += t.x * t.x + t.y * t.y + t.z * t.z + t.w * t.w;
    }
#pragma unroll
    for (int off = 16; off > 0; off >>= 1) {
        s  += __shfl_xor_sync(0xffffffffu, s,  off);
        sq += __shfl_xor_sync(0xffffffffu, sq, off);
    }
    const float mean = s * (1.f / DOUT);
    const float var  = sq * (1.f / DOUT) - mean * mean;
    const float rstd = rsqrtf(var + LN_EPSF);

    float4* op = reinterpret_cast<float4*>(out + (size_t)row * DOUT);
    const float4* gp = reinterpret_cast<const float4*>(gamma);
    const float4* bp = reinterpret_cast<const float4*>(beta);
#pragma unroll
    for (int i = 0; i < 6; ++i) {
        const int idx = i * 32 + lane;
        const float4 g = __ldg(gp + idx);
        const float4 bt = __ldg(bp + idx);
        float4 o;
        o.x = (v[i].x - mean) * rstd * g.x + bt.x;
        o.y = (v[i].y - mean) * rstd * g.y + bt.y;
        o.z = (v[i].z - mean) * rstd * g.z + bt.z;
        o.w = (v[i].w - mean) * rstd * g.w + bt.w;
        op[idx] = o;
    }
}

// ---------------------------------------------------------------------------
extern "C" void kernel_launch(void* const* d_in, const int* in_sizes, int n_in,
                              void* d_out, int out_size)
{
    const float* x     = (const float*)d_in[0];
    const float* W     = (const float*)d_in[1];
    const float* b     = (const float*)d_in[2];
    const float* Wp    = (const float*)d_in[3];
    const float* bp    = (const float*)d_in[4];
    const float* Wc    = (const float*)d_in[5];
    const float* bc    = (const float*)d_in[6];
    const float* scal  = (const float*)d_in[7];
    const float* trans = (const float*)d_in[8];
    const float* gamma = (const float*)d_in[9];
    const float* beta  = (const float*)d_in[10];
    float* out = (float*)d_out;

    cudaFuncSetAttribute(k_wavelet, cudaFuncAttributeMaxDynamicSharedMemorySize, WSMEM);
    cudaFuncSetAttribute(k_gemm_tc, cudaFuncAttributeMaxDynamicSharedMemorySize, TC_SMEM);

    k_split<<<(NW * DIN + 255) / 256, 256>>>(Wp);
    k_wcpad<<<(DOUT * NWP + 255) / 256, 256>>>(Wc);

    k_wavelet<<<NROWS / 128, 256, WSMEM>>>(x, bp, scal, trans);

    dim3 g2(DOUT / TC_BN, NROWS / TC_BM);   // (3, 256)
    k_gemm_tc<<<g2, 256, TC_SMEM>>>(x, W, b, bc);

    k_ln<<<NROWS / 8, 256>>>(gamma, beta, out);
}

// round 11
// speedup vs baseline: 2.9797x; 1.1058x over previous
#include <cuda_runtime.h>
#include <cstdint>
#include <math.h>

#define NROWS 32768
#define DIN   768
#define DOUT  768
#define NW    48
#define NH    16
#define NWP   64                 // padded wavelet width (stride of g_wav / g_wc_pad)
#define LN_EPSF 1e-5f

// ---------------- main GEMM tiling (shared by both bodies) ----------------
#define TC_BM 128
#define TC_BN 256
#define TC_NKT 26                // K-tiles of 32 floats (768+64 = 832)
#define TC_STAGES 4
#define A_BYTES (128 * 128)      // 16 KB
#define B_BYTES (256 * 128)      // 32 KB
#define STAGE_BYTES (A_BYTES + B_BYTES)            // 48 KB
#define MBAR_OFF  (TC_STAGES * STAGE_BYTES)        // 196608
#define FULL_OFF  MBAR_OFF                         // 4 x 8
#define EMPTY_OFF (MBAR_OFF + 32)                  // 4 x 8
#define FIN_OFF   (MBAR_OFF + 64)                  // 8
#define TMEMP_OFF (MBAR_OFF + 80)
#define TC_SMEM   (TMEMP_OFF + 16)

// idesc: dtype=F32(1)@[4], atype=TF32(2)@[7], btype=TF32(2)@[10], N/8@[17], M/16@[24]
#define TC_IDESC ((1u << 4) | (2u << 7) | (2u << 10) | ((TC_BN / 8) << 17) | ((TC_BM / 16) << 24))

// SW128 K-major SMEM descriptor: LBO=1, SBO=64, version=1, layout=SW128(2)
#define DESC_BASE ((uint64_t(2) << 61) | (uint64_t(1) << 46) | (uint64_t(64) << 32) | (uint64_t(1) << 16))
#define SW128(o) ((o) ^ (((o) >> 3) & 0x70))

// fallback (mma.sync) layout inside the same smem budget
#define FB_BK  32
#define FB_LDS 36
#define FB_STAGEF ((128 + 256) * FB_LDS)   // floats per stage

// ---------------- wavelet GEMM tiling (mma.sync 3xTF32) ----------------
#define LDSS 52
#define WSTAGES 2
#define NKTW 16
#define WSTAGEF ((128 + 96) * LDSS)
#define WSMEM   (WSTAGES * WSTAGEF * 4)   // 93184 bytes

// Scratch (allocation-free rule: static __device__ arrays)
__device__ float g_wav[(size_t)NROWS * NWP];
__device__ float g_h[(size_t)NROWS * DOUT];
__device__ float g_wp_hi[(size_t)NW * DIN];
__device__ float g_wp_lo[(size_t)NW * DIN];
__device__ float g_wc_pad[(size_t)DOUT * NWP];

// ---------------- helpers ----------------
__device__ __forceinline__ unsigned f2tf32(float f) {
    unsigned r;
    asm("cvt.rna.tf32.f32 %0, %1;" : "=r"(r) : "f"(f));
    return r;
}
__device__ __forceinline__ void tf32_split(float v, unsigned& hi, unsigned& lo) {
    hi = f2tf32(v);
    lo = f2tf32(v - __uint_as_float(hi));
}
__device__ __forceinline__ unsigned smem_u32(const void* p) {
    return (unsigned)__cvta_generic_to_shared(p);
}
__device__ __forceinline__ void cp16(void* smem_dst, const float* gmem_src) {
    asm volatile("cp.async.cg.shared.global [%0], [%1], 16;\n"
                 :: "r"(smem_u32(smem_dst)), "l"(gmem_src));
}
__device__ __forceinline__ void cp_commit() {
    asm volatile("cp.async.commit_group;\n");
}
template <int N>
__device__ __forceinline__ void cp_wait() {
    asm volatile("cp.async.wait_group %0;\n" :: "n"(N));
}
__device__ __forceinline__ void mma_tf32(float* c, const unsigned* a, const unsigned* b) {
    asm volatile(
        "mma.sync.aligned.m16n8k8.row.col.f32.tf32.tf32.f32 "
        "{%0,%1,%2,%3}, {%4,%5,%6,%7}, {%8,%9}, {%0,%1,%2,%3};"
        : "+f"(c[0]), "+f"(c[1]), "+f"(c[2]), "+f"(c[3])
        : "r"(a[0]), "r"(a[1]), "r"(a[2]), "r"(a[3]), "r"(b[0]), "r"(b[1]));
}
__device__ __forceinline__ void mbar_wait_par(unsigned mbar, unsigned parity) {
    asm volatile(
        "{\n\t.reg .pred P;\n\t"
        "W_%=: mbarrier.try_wait.parity.shared.b64 P, [%0], %1;\n\t"
        "@P bra D_%=;\n\t"
        "bra W_%=;\n\t"
        "D_%=:\n\t}"
        :: "r"(mbar), "r"(parity) : "memory");
}

// ---------------------------------------------------------------------------
// Kernel 0a: pre-split Wp into tf32 hi/lo
// ---------------------------------------------------------------------------
__global__ void k_split(const float* __restrict__ Wp) {
    const int i = blockIdx.x * 256 + threadIdx.x;
    if (i < NW * DIN) {
        const float v = Wp[i];
        const float hi = __uint_as_float(f2tf32(v));
        g_wp_hi[i] = hi;
        g_wp_lo[i] = __uint_as_float(f2tf32(v - hi));
    }
}

// ---------------------------------------------------------------------------
// Kernel 0b: repack Wc [DOUT,48] -> g_wc_pad [DOUT,64] zero-padded
// ---------------------------------------------------------------------------
__global__ void k_wcpad(const float* __restrict__ Wc) {
    const int i = blockIdx.x * 256 + threadIdx.x;
    if (i < DOUT * NWP) {
        const int n = i >> 6, k = i & 63;
        g_wc_pad[i] = (k < NW) ? Wc[n * NW + k] : 0.f;
    }
}

// ---------------------------------------------------------------------------
// Kernel 1: wavelet path, 3xTF32 mma.sync GEMM; output stride 64, pad zeroed
// ---------------------------------------------------------------------------
__global__ __launch_bounds__(256, 2) void k_wavelet(
    const float* __restrict__ x,
    const float* __restrict__ bp, const float* __restrict__ scales,
    const float* __restrict__ trans)
{
    extern __shared__ float sm[];
    const int tid  = threadIdx.x;
    const int lane = tid & 31;
    const int warp = tid >> 5;
    const int rowBase = blockIdx.x * 128;
    const int r0 = lane >> 2;
    const int kq = lane & 3;

    float acc[6][4];
#pragma unroll
    for (int nt = 0; nt < 6; ++nt)
#pragma unroll
        for (int c = 0; c < 4; ++c) acc[nt][c] = 0.f;

    auto load_tile = [&](int st, int kt) {
        float* Xs = sm + st * WSTAGEF;
        float* Ws = Xs + 128 * LDSS;
#pragma unroll
        for (int i = 0; i < 6; ++i) {
            const int idx = i * 256 + tid;
            const int row = idx / 12, c4 = idx % 12;
            cp16(&Xs[row * LDSS + c4 * 4],
                 x + (size_t)(rowBase + row) * DIN + kt * 48 + c4 * 4);
        }
#pragma unroll
        for (int i = 0; i < 5; ++i) {
            const int idx = i * 256 + tid;
            if (idx < 1152) {
                const int row = idx / 12, c4 = idx % 12;
                const float* src = (row < 48)
                    ? g_wp_hi + (size_t)row * DIN + kt * 48 + c4 * 4
                    : g_wp_lo + (size_t)(row - 48) * DIN + kt * 48 + c4 * 4;
                cp16(&Ws[row * LDSS + c4 * 4], src);
            }
        }
    };

#pragma unroll
    for (int s = 0; s < WSTAGES; ++s) { load_tile(s, s); cp_commit(); }

    for (int kt = 0; kt < NKTW; ++kt) {
        cp_wait<WSTAGES - 1>();
        __syncthreads();
        const int st = kt % WSTAGES;
        const float* Xs = sm + st * WSTAGEF;
        const float* Ws = Xs + 128 * LDSS;
        const int m = warp * 16;
#pragma unroll
        for (int ks = 0; ks < 6; ++ks) {
            const int ko = ks * 8;
            unsigned ah[4], al[4];
            tf32_split(Xs[(m + r0) * LDSS + ko + kq],          ah[0], al[0]);
            tf32_split(Xs[(m + r0 + 8) * LDSS + ko + kq],      ah[1], al[1]);
            tf32_split(Xs[(m + r0) * LDSS + ko + kq + 4],      ah[2], al[2]);
            tf32_split(Xs[(m + r0 + 8) * LDSS + ko + kq + 4],  ah[3], al[3]);
#pragma unroll
            for (int nt = 0; nt < 6; ++nt) {
                unsigned bh[2], bl[2];
                bh[0] = __float_as_uint(Ws[(nt * 8 + r0) * LDSS + ko + kq]);
                bh[1] = __float_as_uint(Ws[(nt * 8 + r0) * LDSS + ko + kq + 4]);
                bl[0] = __float_as_uint(Ws[(48 + nt * 8 + r0) * LDSS + ko + kq]);
                bl[1] = __float_as_uint(Ws[(48 + nt * 8 + r0) * LDSS + ko + kq + 4]);
                mma_tf32(acc[nt], ah, bl);
                mma_tf32(acc[nt], al, bh);
                mma_tf32(acc[nt], ah, bh);
            }
        }
        __syncthreads();
        if (kt + WSTAGES < NKTW) load_tile(st, kt + WSTAGES);
        cp_commit();
    }

    // zero the pad columns 48..63 for this block's 128 rows
#pragma unroll
    for (int i = 0; i < 8; ++i) {
        const int idx = i * 256 + tid;          // 0..2047
        const int row = idx >> 4, col = 48 + (idx & 15);
        g_wav[(size_t)(rowBase + row) * NWP + col] = 0.f;
    }

    const int rA = rowBase + warp * 16 + r0;
#pragma unroll
    for (int nt = 0; nt < 6; ++nt) {
        const int j0 = nt * 8 + 2 * kq;
        const float bp0 = __ldg(bp + j0),     bp1 = __ldg(bp + j0 + 1);
        const float t0  = __ldg(trans + j0),  t1  = __ldg(trans + j0 + 1);
        const float sc0 = __ldg(scales + j0), sc1 = __ldg(scales + j0 + 1);
#pragma unroll
        for (int half = 0; half < 2; ++half) {
            const int r = rA + half * 8;
            const float s0 = (acc[nt][half * 2 + 0] + bp0 - t0) / sc0;
            const float s1 = (acc[nt][half * 2 + 1] + bp1 - t1) / sc1;
            float w0, w1;
            if (nt < 2) {               // haar
                w0 = (s0 >= 0.f && s0 < 0.5f) ? 1.f : ((s0 >= 0.5f && s0 < 1.f) ? -1.f : 0.f);
                w1 = (s1 >= 0.f && s1 < 0.5f) ? 1.f : ((s1 >= 0.5f && s1 < 1.f) ? -1.f : 0.f);
            } else if (nt < 4) {        // mexican hat
                w0 = (1.f - s0 * s0) * expf(-0.5f * s0 * s0);
                w1 = (1.f - s1 * s1) * expf(-0.5f * s1 * s1);
            } else {                    // morlet
                w0 = cosf(5.0f * s0) * expf(-0.5f * s0 * s0);
                w1 = cosf(5.0f * s1) * expf(-0.5f * s1 * s1);
            }
            float2 o;
            o.x = 0.5f * w0 * (1.f + erff(w0 * 0.7071067811865475f));
            o.y = 0.5f * w1 * (1.f + erff(w1 * 0.7071067811865475f));
            *reinterpret_cast<float2*>(&g_wav[(size_t)r * NWP + j0]) = o;
        }
    }
}

// ---------------------------------------------------------------------------
// Kernel 2: main GEMM. sm_103a -> tcgen05 warp-specialized mbarrier pipeline
//           sm_103  -> mma.sync fallback (same launch config)
// ---------------------------------------------------------------------------
__global__ __launch_bounds__(256, 1) void k_gemm_tc(
    const float* __restrict__ x, const float* __restrict__ W,
    const float* __restrict__ b, const float* __restrict__ bc)
{
#if defined(__CUDA_ARCH__) && defined(__CUDA_ARCH_FEAT_SM103_ALL)
    // ==================== tcgen05 body ====================
    extern __shared__ char smc[];
    const unsigned smem_base = smem_u32(smc);
    const int tid  = threadIdx.x;
    const int lane = tid & 31;
    const int warp = tid >> 5;
    const int rowBase = blockIdx.y * TC_BM;
    const int colBase = blockIdx.x * TC_BN;

    if (warp == 0) {
        asm volatile("tcgen05.alloc.cta_group::1.sync.aligned.shared::cta.b32 [%0], %1;"
                     :: "r"(smem_base + TMEMP_OFF), "r"(256u) : "memory");
    }
    if (tid == 0) {
#pragma unroll
        for (int s = 0; s < TC_STAGES; ++s) {
            asm volatile("mbarrier.init.shared.b64 [%0], 192;"
                         :: "r"(smem_base + FULL_OFF + s * 8) : "memory");
            asm volatile("mbarrier.init.shared.b64 [%0], 1;"
                         :: "r"(smem_base + EMPTY_OFF + s * 8) : "memory");
        }
        asm volatile("mbarrier.init.shared.b64 [%0], 1;"
                     :: "r"(smem_base + FIN_OFF) : "memory");
    }
    __syncthreads();
    unsigned tmem_base;
    asm volatile("ld.shared.b32 %0, [%1];" : "=r"(tmem_base) : "r"(smem_base + TMEMP_OFF));

    if (tid < 192) {
        // ---------------- producer role ----------------
        const bool isA = (tid < 64);
        const int t = isA ? tid : (tid - 64);
        for (int kt = 0; kt < TC_NKT; ++kt) {
            const int st = kt & 3;
            const unsigned par = ((kt >> 2) & 1) ^ 1;   // first use passes immediately
            mbar_wait_par(smem_base + EMPTY_OFF + st * 8, par);

            char* At = smc + st * STAGE_BYTES;
            char* Bt = At + A_BYTES;
            const bool mainseg = (kt < 24);
            const int kk = mainseg ? kt * 32 : (kt - 24) * 32;
            if (isA) {
                const float* src = mainseg ? (x + (size_t)rowBase * DIN + kk)
                                           : (g_wav + (size_t)rowBase * NWP + kk);
                const int stride = mainseg ? DIN : NWP;
#pragma unroll
                for (int i = 0; i < 16; ++i) {
                    const int idx = i * 64 + t;           // 0..1023
                    const int row = idx >> 3, c = idx & 7;
                    cp16(At + SW128(row * 128 + c * 16), src + (size_t)row * stride + c * 4);
                }
            } else {
                const float* src = mainseg ? (W + (size_t)colBase * DIN + kk)
                                           : (g_wc_pad + (size_t)colBase * NWP + kk);
                const int stride = mainseg ? DIN : NWP;
#pragma unroll
                for (int i = 0; i < 16; ++i) {
                    const int idx = i * 128 + t;          // 0..2047
                    const int row = idx >> 3, c = idx & 7;
                    cp16(Bt + SW128(row * 128 + c * 16), src + (size_t)row * stride + c * 4);
                }
            }
            asm volatile("cp.async.mbarrier.arrive.noinc.shared.b64 [%0];"
                         :: "r"(smem_base + FULL_OFF + st * 8) : "memory");
        }
    } else if (tid == 192) {
        // ---------------- MMA issue role ----------------
        for (int kt = 0; kt < TC_NKT; ++kt) {
            const int st = kt & 3;
            mbar_wait_par(smem_base + FULL_OFF + st * 8, (kt >> 2) & 1);
            asm volatile("fence.proxy.async.shared::cta;" ::: "memory");
            const uint64_t adesc = DESC_BASE |
                (uint64_t)(((smem_base + st * STAGE_BYTES) >> 4) & 0x3FFF);
            const uint64_t bdesc = DESC_BASE |
                (uint64_t)(((smem_base + st * STAGE_BYTES + A_BYTES) >> 4) & 0x3FFF);
#pragma unroll
            for (int step = 0; step < 4; ++step) {
                const unsigned en = (kt > 0 || step > 0) ? 1u : 0u;
                asm volatile(
                    "{\n\t.reg .pred p;\n\t"
                    "setp.ne.u32 p, %4, 0;\n\t"
                    "tcgen05.mma.cta_group::1.kind::tf32 [%0], %1, %2, %3, {%5, %5, %5, %5}, p;\n\t}"
                    :: "r"(tmem_base), "l"(adesc + step * 2), "l"(bdesc + step * 2),
                       "r"((unsigned)TC_IDESC), "r"(en), "r"(0u)
                    : "memory");
            }
            asm volatile(
                "tcgen05.commit.cta_group::1.mbarrier::arrive::one.shared::cluster.b64 [%0];"
                :: "r"(smem_base + EMPTY_OFF + st * 8) : "memory");
        }
        asm volatile(
            "tcgen05.commit.cta_group::1.mbarrier::arrive::one.shared::cluster.b64 [%0];"
            :: "r"(smem_base + FIN_OFF) : "memory");
    }

    // ---------------- all threads: wait for final MMA completion ----------------
    mbar_wait_par(smem_base + FIN_OFF, 0);
    asm volatile("tcgen05.fence::after_thread_sync;" ::: "memory");

    const int sub = warp & 3;
    const int colBlk = (warp >> 2) * 128;
    const int row = rowBase + sub * 32 + lane;
#pragma unroll
    for (int chunk = 0; chunk < 4; ++chunk) {
        unsigned r[32];
        asm volatile(
            "tcgen05.ld.sync.aligned.32x32b.x32.b32 "
            "{%0, %1, %2, %3, %4, %5, %6, %7, %8, %9, %10, %11, %12, %13, %14, %15, "
            " %16, %17, %18, %19, %20, %21, %22, %23, %24, %25, %26, %27, %28, %29, %30, %31}, [%32];"
            : "=r"(r[0]), "=r"(r[1]), "=r"(r[2]), "=r"(r[3]), "=r"(r[4]), "=r"(r[5]),
              "=r"(r[6]), "=r"(r[7]), "=r"(r[8]), "=r"(r[9]), "=r"(r[10]), "=r"(r[11]),
              "=r"(r[12]), "=r"(r[13]), "=r"(r[14]), "=r"(r[15]), "=r"(r[16]), "=r"(r[17]),
              "=r"(r[18]), "=r"(r[19]), "=r"(r[20]), "=r"(r[21]), "=r"(r[22]), "=r"(r[23]),
              "=r"(r[24]), "=r"(r[25]), "=r"(r[26]), "=r"(r[27]), "=r"(r[28]), "=r"(r[29]),
              "=r"(r[30]), "=r"(r[31])
            : "r"(tmem_base + colBlk + chunk * 32));
        asm volatile("tcgen05.wait::ld.sync.aligned;" ::: "memory");
        const int c0 = colBase + colBlk + chunk * 32;
#pragma unroll
        for (int q = 0; q < 8; ++q) {
            const int cc = c0 + q * 4;
            float4 v;
            v.x = __uint_as_float(r[q * 4 + 0]) + __ldg(b + cc)     + __ldg(bc + cc);
            v.y = __uint_as_float(r[q * 4 + 1]) + __ldg(b + cc + 1) + __ldg(bc + cc + 1);
            v.z = __uint_as_float(r[q * 4 + 2]) + __ldg(b + cc + 2) + __ldg(bc + cc + 2);
            v.w = __uint_as_float(r[q * 4 + 3]) + __ldg(b + cc + 3) + __ldg(bc + cc + 3);
            *reinterpret_cast<float4*>(&g_h[(size_t)row * DOUT + cc]) = v;
        }
    }

    __syncthreads();
    if (warp == 0) {
        asm volatile("tcgen05.dealloc.cta_group::1.sync.aligned.b32 %0, %1;"
                     :: "r"(tmem_base), "r"(256u));
    }
#else
    // ==================== mma.sync fallback body ====================
    extern __shared__ float smf[];
    const int tid  = threadIdx.x;
    const int lane = tid & 31;
    const int warp = tid >> 5;
    const int wm = warp >> 2;            // 0..1 -> 64 rows
    const int wn = warp & 3;             // 0..3 -> 64 cols
    const int rowBase = blockIdx.y * TC_BM;
    const int colBase = blockIdx.x * TC_BN;
    const int r0 = lane >> 2;
    const int kq = lane & 3;

    float acc[4][8][4];
#pragma unroll
    for (int i = 0; i < 4; ++i)
#pragma unroll
        for (int j = 0; j < 8; ++j)
#pragma unroll
            for (int c = 0; c < 4; ++c) acc[i][j][c] = 0.f;

    auto load_tile = [&](int st, int kt) {
        float* As = smf + st * FB_STAGEF;
        float* Bs = As + 128 * FB_LDS;
        const bool mainseg = (kt < 24);
        const int kk = mainseg ? kt * 32 : (kt - 24) * 32;
        const float* aB = mainseg ? x : g_wav;
        const float* bB = mainseg ? W : g_wc_pad;
        const int aStride = mainseg ? DIN : NWP;
#pragma unroll
        for (int i = 0; i < 4; ++i) {
            const int idx = i * 256 + tid;
            const int row = idx >> 3, c = idx & 7;
            cp16(&As[row * FB_LDS + c * 4],
                 aB + (size_t)(rowBase + row) * aStride + kk + c * 4);
        }
#pragma unroll
        for (int i = 0; i < 8; ++i) {
            const int idx = i * 256 + tid;
            const int row = idx >> 3, c = idx & 7;
            cp16(&Bs[row * FB_LDS + c * 4],
                 bB + (size_t)(colBase + row) * aStride + kk + c * 4);
        }
    };

#pragma unroll
    for (int s = 0; s < 2; ++s) { load_tile(s, s); cp_commit(); }

    for (int kt = 0; kt < TC_NKT; ++kt) {
        cp_wait<1>();
        __syncthreads();
        const int st = kt & 1;
        const float* As = smf + st * FB_STAGEF;
        const float* Bs = As + 128 * FB_LDS;
#pragma unroll
        for (int ks = 0; ks < 4; ++ks) {
            const int ko = ks * 8;
            unsigned af[4][4];
            unsigned bf[8][2];
#pragma unroll
            for (int im = 0; im < 4; ++im) {
                const int m = wm * 64 + im * 16;
                af[im][0] = f2tf32(As[(m + r0) * FB_LDS + ko + kq]);
                af[im][1] = f2tf32(As[(m + r0 + 8) * FB_LDS + ko + kq]);
                af[im][2] = f2tf32(As[(m + r0) * FB_LDS + ko + kq + 4]);
                af[im][3] = f2tf32(As[(m + r0 + 8) * FB_LDS + ko + kq + 4]);
            }
#pragma unroll
            for (int in = 0; in < 8; ++in) {
                const int n = wn * 64 + in * 8;
                bf[in][0] = f2tf32(Bs[(n + r0) * FB_LDS + ko + kq]);
                bf[in][1] = f2tf32(Bs[(n + r0) * FB_LDS + ko + kq + 4]);
            }
#pragma unroll
            for (int im = 0; im < 4; ++im)
#pragma unroll
                for (int in = 0; in < 8; ++in)
                    mma_tf32(acc[im][in], af[im], bf[in]);
        }
        __syncthreads();
        if (kt + 2 < TC_NKT) load_tile(st, kt + 2);
        cp_commit();
    }

#pragma unroll
    for (int im = 0; im < 4; ++im) {
        const int r = rowBase + wm * 64 + im * 16 + r0;
#pragma unroll
        for (int in = 0; in < 8; ++in) {
            const int cc = colBase + wn * 64 + in * 8 + 2 * kq;
            const float b0 = __ldg(b + cc) + __ldg(bc + cc);
            const float b1 = __ldg(b + cc + 1) + __ldg(bc + cc + 1);
            float2 v;
            v.x = acc[im][in][0] + b0; v.y = acc[im][in][1] + b1;
            *reinterpret_cast<float2*>(&g_h[(size_t)r * DOUT + cc]) = v;
            v.x = acc[im][in][2] + b0; v.y = acc[im][in][3] + b1;
            *reinterpret_cast<float2*>(&g_h[(size_t)(r + 8) * DOUT + cc]) = v;
        }
    }
#endif
}

// ---------------------------------------------------------------------------
// Kernel 3: LayerNorm over DOUT=768, warp per row
// ---------------------------------------------------------------------------
__global__ __launch_bounds__(256) void k_ln(
    const float* __restrict__ gamma, const float* __restrict__ beta,
    float* __restrict__ out)
{
    const int lane = threadIdx.x & 31;
    const int warp = threadIdx.x >> 5;
    const int row = blockIdx.x * 8 + warp;

    const float4* hp = reinterpret_cast<const float4*>(g_h + (size_t)row * DOUT);
    float4 v[6];
    float s = 0.f, sq = 0.f;
#pragma unroll
    for (int i = 0; i < 6; ++i) {
        const float4 t = hp[i * 32 + lane];
        v[i] = t;
        s  += t.x + t.y + t.z + t.w;
        sq += t.x * t.x + t.y * t.y + t.z * t.z + t.w * t.w;
    }
#pragma unroll
    for (int off = 16; off > 0; off >>= 1) {
        s  += __shfl_xor_sync(0xffffffffu, s,  off);
        sq += __shfl_xor_sync(0xffffffffu, sq, off);
    }
    const float mean = s * (1.f / DOUT);
    const float var  = sq * (1.f / DOUT) - mean * mean;
    const float rstd = rsqrtf(var + LN_EPSF);

    float4* op = reinterpret_cast<float4*>(out + (size_t)row * DOUT);
    const float4* gp = reinterpret_cast<const float4*>(gamma);
    const float4* bp = reinterpret_cast<const float4*>(beta);
#pragma unroll
    for (int i = 0; i < 6; ++i) {
        const int idx = i * 32 + lane;
        const float4 g = __ldg(gp + idx);
        const float4 bt = __ldg(bp + idx);
        float4 o;
        o.x = (v[i].x - mean) * rstd * g.x + bt.x;
        o.y = (v[i].y - mean) * rstd * g.y + bt.y;
        o.z = (v[i].z - mean) * rstd * g.z + bt.z;
        o.w = (v[i].w - mean) * rstd * g.w + bt.w;
        op[idx] = o;
    }
}

// ---------------------------------------------------------------------------
extern "C" void kernel_launch(void* const* d_in, const int* in_sizes, int n_in,
                              void* d_out, int out_size)
{
    const float* x     = (const float*)d_in[0];
    const float* W     = (const float*)d_in[1];
    const float* b     = (const float*)d_in[2];
    const float* Wp    = (const float*)d_in[3];
    const float* bp    = (const float*)d_in[4];
    const float* Wc    = (const float*)d_in[5];
    const float* bc    = (const float*)d_in[6];
    const float* scal  = (const float*)d_in[7];
    const float* trans = (const float*)d_in[8];
    const float* gamma = (const float*)d_in[9];
    const float* beta  = (const float*)d_in[10];
    float* out = (float*)d_out;

    cudaFuncSetAttribute(k_wavelet, cudaFuncAttributeMaxDynamicSharedMemorySize, WSMEM);
    cudaFuncSetAttribute(k_gemm_tc, cudaFuncAttributeMaxDynamicSharedMemorySize, TC_SMEM);

    k_split<<<(NW * DIN + 255) / 256, 256>>>(Wp);
    k_wcpad<<<(DOUT * NWP + 255) / 256, 256>>>(Wc);

    k_wavelet<<<NROWS / 128, 256, WSMEM>>>(x, bp, scal, trans);

    dim3 g2(DOUT / TC_BN, NROWS / TC_BM);   // (3, 256)
    k_gemm_tc<<<g2, 256, TC_SMEM>>>(x, W, b, bc);

    k_ln<<<NROWS / 8, 256>>>(gamma, beta, out);
}

// round 12
// speedup vs baseline: 3.0945x; 1.0385x over previous
#include <cuda_runtime.h>
#include <cuda.h>
#include <cstdint>
#include <math.h>

#define NROWS 32768
#define DIN   768
#define DOUT  768
#define NW    48
#define NH    16
#define NWP   64                 // padded wavelet width (stride of g_wav / g_wc_pad)
#define LN_EPSF 1e-5f

// ---------------- main GEMM tiling (shared by both bodies) ----------------
#define TC_BM 128
#define TC_BN 256
#define TC_NKT 26                // K-tiles of 32 floats (768+64 = 832)
#define TC_STAGES 4
#define A_BYTES (128 * 128)      // 16 KB
#define B_BYTES (256 * 128)      // 32 KB
#define STAGE_BYTES (A_BYTES + B_BYTES)            // 48 KB
#define MBAR_OFF  (TC_STAGES * STAGE_BYTES)        // 196608
#define FULL_OFF  MBAR_OFF                         // 4 x 8
#define EMPTY_OFF (MBAR_OFF + 32)                  // 4 x 8
#define FIN_OFF   (MBAR_OFF + 64)                  // 8
#define TMEMP_OFF (MBAR_OFF + 80)
#define TC_SMEM   (TMEMP_OFF + 16)

// idesc: dtype=F32(1)@[4], atype=TF32(2)@[7], btype=TF32(2)@[10], N/8@[17], M/16@[24]
#define TC_IDESC ((1u << 4) | (2u << 7) | (2u << 10) | ((TC_BN / 8) << 17) | ((TC_BM / 16) << 24))

// SW128 K-major SMEM descriptor: LBO=1, SBO=64, version=1, layout=SW128(2)
#define DESC_BASE ((uint64_t(2) << 61) | (uint64_t(1) << 46) | (uint64_t(64) << 32) | (uint64_t(1) << 16))
#define SW128(o) ((o) ^ (((o) >> 3) & 0x70))

// fallback (mma.sync) layout inside the same smem budget
#define FB_LDS 36
#define FB_STAGEF ((128 + 256) * FB_LDS)   // floats per stage

// ---------------- wavelet GEMM tiling (mma.sync 3xTF32) ----------------
#define LDSS 52
#define WSTAGES 2
#define NKTW 16
#define WSTAGEF ((128 + 96) * LDSS)
#define WSMEM   (WSTAGES * WSTAGEF * 4)   // 93184 bytes

// Scratch (allocation-free rule: static __device__ arrays)
__device__ float g_wav[(size_t)NROWS * NWP];
__device__ float g_h[(size_t)NROWS * DOUT];
__device__ float g_wp_hi[(size_t)NW * DIN];
__device__ float g_wp_lo[(size_t)NW * DIN];
__device__ float g_wc_pad[(size_t)DOUT * NWP];

// ---------------- helpers ----------------
__device__ __forceinline__ unsigned f2tf32(float f) {
    unsigned r;
    asm("cvt.rna.tf32.f32 %0, %1;" : "=r"(r) : "f"(f));
    return r;
}
__device__ __forceinline__ void tf32_split(float v, unsigned& hi, unsigned& lo) {
    hi = f2tf32(v);
    lo = f2tf32(v - __uint_as_float(hi));
}
__device__ __forceinline__ unsigned smem_u32(const void* p) {
    return (unsigned)__cvta_generic_to_shared(p);
}
__device__ __forceinline__ void cp16(void* smem_dst, const float* gmem_src) {
    asm volatile("cp.async.cg.shared.global [%0], [%1], 16;\n"
                 :: "r"(smem_u32(smem_dst)), "l"(gmem_src));
}
__device__ __forceinline__ void cp_commit() {
    asm volatile("cp.async.commit_group;\n");
}
template <int N>
__device__ __forceinline__ void cp_wait() {
    asm volatile("cp.async.wait_group %0;\n" :: "n"(N));
}
__device__ __forceinline__ void mma_tf32(float* c, const unsigned* a, const unsigned* b) {
    asm volatile(
        "mma.sync.aligned.m16n8k8.row.col.f32.tf32.tf32.f32 "
        "{%0,%1,%2,%3}, {%4,%5,%6,%7}, {%8,%9}, {%0,%1,%2,%3};"
        : "+f"(c[0]), "+f"(c[1]), "+f"(c[2]), "+f"(c[3])
        : "r"(a[0]), "r"(a[1]), "r"(a[2]), "r"(a[3]), "r"(b[0]), "r"(b[1]));
}
__device__ __forceinline__ void mbar_wait_par(unsigned mbar, unsigned parity) {
    asm volatile(
        "{\n\t.reg .pred P;\n\t"
        "W_%=: mbarrier.try_wait.parity.shared.b64 P, [%0], %1;\n\t"
        "@P bra D_%=;\n\t"
        "bra W_%=;\n\t"
        "D_%=:\n\t}"
        :: "r"(mbar), "r"(parity) : "memory");
}
__device__ __forceinline__ void tma2d(unsigned smem_dst, const void* map,
                                      int c0, int c1, unsigned mbar) {
    asm volatile(
        "cp.async.bulk.tensor.2d.shared::cta.global.tile.mbarrier::complete_tx::bytes "
        "[%0], [%1, {%2, %3}], [%4];"
        :: "r"(smem_dst), "l"(map), "r"(c0), "r"(c1), "r"(mbar) : "memory");
}

// ---------------------------------------------------------------------------
// Kernel 0a: pre-split Wp into tf32 hi/lo
// ---------------------------------------------------------------------------
__global__ void k_split(const float* __restrict__ Wp) {
    const int i = blockIdx.x * 256 + threadIdx.x;
    if (i < NW * DIN) {
        const float v = Wp[i];
        const float hi = __uint_as_float(f2tf32(v));
        g_wp_hi[i] = hi;
        g_wp_lo[i] = __uint_as_float(f2tf32(v - hi));
    }
}

// ---------------------------------------------------------------------------
// Kernel 0b: repack Wc [DOUT,48] -> g_wc_pad [DOUT,64] zero-padded
// ---------------------------------------------------------------------------
__global__ void k_wcpad(const float* __restrict__ Wc) {
    const int i = blockIdx.x * 256 + threadIdx.x;
    if (i < DOUT * NWP) {
        const int n = i >> 6, k = i & 63;
        g_wc_pad[i] = (k < NW) ? Wc[n * NW + k] : 0.f;
    }
}

// ---------------------------------------------------------------------------
// Kernel 1: wavelet path, 3xTF32 mma.sync GEMM; output stride 64, pad zeroed
// ---------------------------------------------------------------------------
__global__ __launch_bounds__(256, 2) void k_wavelet(
    const float* __restrict__ x,
    const float* __restrict__ bp, const float* __restrict__ scales,
    const float* __restrict__ trans)
{
    extern __shared__ float sm[];
    const int tid  = threadIdx.x;
    const int lane = tid & 31;
    const int warp = tid >> 5;
    const int rowBase = blockIdx.x * 128;
    const int r0 = lane >> 2;
    const int kq = lane & 3;

    float acc[6][4];
#pragma unroll
    for (int nt = 0; nt < 6; ++nt)
#pragma unroll
        for (int c = 0; c < 4; ++c) acc[nt][c] = 0.f;

    auto load_tile = [&](int st, int kt) {
        float* Xs = sm + st * WSTAGEF;
        float* Ws = Xs + 128 * LDSS;
#pragma unroll
        for (int i = 0; i < 6; ++i) {
            const int idx = i * 256 + tid;
            const int row = idx / 12, c4 = idx % 12;
            cp16(&Xs[row * LDSS + c4 * 4],
                 x + (size_t)(rowBase + row) * DIN + kt * 48 + c4 * 4);
        }
#pragma unroll
        for (int i = 0; i < 5; ++i) {
            const int idx = i * 256 + tid;
            if (idx < 1152) {
                const int row = idx / 12, c4 = idx % 12;
                const float* src = (row < 48)
                    ? g_wp_hi + (size_t)row * DIN + kt * 48 + c4 * 4
                    : g_wp_lo + (size_t)(row - 48) * DIN + kt * 48 + c4 * 4;
                cp16(&Ws[row * LDSS + c4 * 4], src);
            }
        }
    };

#pragma unroll
    for (int s = 0; s < WSTAGES; ++s) { load_tile(s, s); cp_commit(); }

    for (int kt = 0; kt < NKTW; ++kt) {
        cp_wait<WSTAGES - 1>();
        __syncthreads();
        const int st = kt % WSTAGES;
        const float* Xs = sm + st * WSTAGEF;
        const float* Ws = Xs + 128 * LDSS;
        const int m = warp * 16;
#pragma unroll
        for (int ks = 0; ks < 6; ++ks) {
            const int ko = ks * 8;
            unsigned ah[4], al[4];
            tf32_split(Xs[(m + r0) * LDSS + ko + kq],          ah[0], al[0]);
            tf32_split(Xs[(m + r0 + 8) * LDSS + ko + kq],      ah[1], al[1]);
            tf32_split(Xs[(m + r0) * LDSS + ko + kq + 4],      ah[2], al[2]);
            tf32_split(Xs[(m + r0 + 8) * LDSS + ko + kq + 4],  ah[3], al[3]);
#pragma unroll
            for (int nt = 0; nt < 6; ++nt) {
                unsigned bh[2], bl[2];
                bh[0] = __float_as_uint(Ws[(nt * 8 + r0) * LDSS + ko + kq]);
                bh[1] = __float_as_uint(Ws[(nt * 8 + r0) * LDSS + ko + kq + 4]);
                bl[0] = __float_as_uint(Ws[(48 + nt * 8 + r0) * LDSS + ko + kq]);
                bl[1] = __float_as_uint(Ws[(48 + nt * 8 + r0) * LDSS + ko + kq + 4]);
                mma_tf32(acc[nt], ah, bl);
                mma_tf32(acc[nt], al, bh);
                mma_tf32(acc[nt], ah, bh);
            }
        }
        __syncthreads();
        if (kt + WSTAGES < NKTW) load_tile(st, kt + WSTAGES);
        cp_commit();
    }

    // zero the pad columns 48..63 for this block's 128 rows
#pragma unroll
    for (int i = 0; i < 8; ++i) {
        const int idx = i * 256 + tid;          // 0..2047
        const int row = idx >> 4, col = 48 + (idx & 15);
        g_wav[(size_t)(rowBase + row) * NWP + col] = 0.f;
    }

    const int rA = rowBase + warp * 16 + r0;
#pragma unroll
    for (int nt = 0; nt < 6; ++nt) {
        const int j0 = nt * 8 + 2 * kq;
        const float bp0 = __ldg(bp + j0),     bp1 = __ldg(bp + j0 + 1);
        const float t0  = __ldg(trans + j0),  t1  = __ldg(trans + j0 + 1);
        const float sc0 = __ldg(scales + j0), sc1 = __ldg(scales + j0 + 1);
#pragma unroll
        for (int half = 0; half < 2; ++half) {
            const int r = rA + half * 8;
            const float s0 = (acc[nt][half * 2 + 0] + bp0 - t0) / sc0;
            const float s1 = (acc[nt][half * 2 + 1] + bp1 - t1) / sc1;
            float w0, w1;
            if (nt < 2) {               // haar
                w0 = (s0 >= 0.f && s0 < 0.5f) ? 1.f : ((s0 >= 0.5f && s0 < 1.f) ? -1.f : 0.f);
                w1 = (s1 >= 0.f && s1 < 0.5f) ? 1.f : ((s1 >= 0.5f && s1 < 1.f) ? -1.f : 0.f);
            } else if (nt < 4) {        // mexican hat
                w0 = (1.f - s0 * s0) * expf(-0.5f * s0 * s0);
                w1 = (1.f - s1 * s1) * expf(-0.5f * s1 * s1);
            } else {                    // morlet
                w0 = cosf(5.0f * s0) * expf(-0.5f * s0 * s0);
                w1 = cosf(5.0f * s1) * expf(-0.5f * s1 * s1);
            }
            float2 o;
            o.x = 0.5f * w0 * (1.f + erff(w0 * 0.7071067811865475f));
            o.y = 0.5f * w1 * (1.f + erff(w1 * 0.7071067811865475f));
            *reinterpret_cast<float2*>(&g_wav[(size_t)r * NWP + j0]) = o;
        }
    }
}

// ---------------------------------------------------------------------------
// Kernel 2: main GEMM. sm_103a -> tcgen05 + TMA warp-specialized pipeline
//           sm_103  -> mma.sync fallback (uses raw x/W pointers)
// ---------------------------------------------------------------------------
__global__ __launch_bounds__(256, 1) void k_gemm_tc(
    const __grid_constant__ CUtensorMap mapX,
    const __grid_constant__ CUtensorMap mapW,
    const __grid_constant__ CUtensorMap mapAV,
    const __grid_constant__ CUtensorMap mapCV,
    const float* __restrict__ x, const float* __restrict__ W,
    const float* __restrict__ b, const float* __restrict__ bc)
{
#if defined(__CUDA_ARCH__) && defined(__CUDA_ARCH_FEAT_SM103_ALL)
    // ==================== tcgen05 + TMA body ====================
    extern __shared__ __align__(1024) char smc[];
    const unsigned smem_base = smem_u32(smc);
    const int tid  = threadIdx.x;
    const int lane = tid & 31;
    const int warp = tid >> 5;
    const int rowBase = blockIdx.y * TC_BM;
    const int colBase = blockIdx.x * TC_BN;

    if (warp == 0) {
        asm volatile("tcgen05.alloc.cta_group::1.sync.aligned.shared::cta.b32 [%0], %1;"
                     :: "r"(smem_base + TMEMP_OFF), "r"(256u) : "memory");
    }
    if (tid == 0) {
#pragma unroll
        for (int s = 0; s < TC_STAGES; ++s) {
            asm volatile("mbarrier.init.shared.b64 [%0], 1;"
                         :: "r"(smem_base + FULL_OFF + s * 8) : "memory");
            asm volatile("mbarrier.init.shared.b64 [%0], 1;"
                         :: "r"(smem_base + EMPTY_OFF + s * 8) : "memory");
        }
        asm volatile("mbarrier.init.shared.b64 [%0], 1;"
                     :: "r"(smem_base + FIN_OFF) : "memory");
    }
    __syncthreads();
    unsigned tmem_base;
    asm volatile("ld.shared.b32 %0, [%1];" : "=r"(tmem_base) : "r"(smem_base + TMEMP_OFF));

    if (warp == 0) {
        // ---------------- TMA producer (lane 0 issues; warp stays converged) ----
        for (int kt = 0; kt < TC_NKT; ++kt) {
            const int st = kt & 3;
            const unsigned par = ((kt >> 2) & 1) ^ 1;   // first use passes immediately
            mbar_wait_par(smem_base + EMPTY_OFF + st * 8, par);
            if (lane == 0) {
                const unsigned fullb = smem_base + FULL_OFF + st * 8;
                asm volatile("mbarrier.arrive.expect_tx.shared.b64 _, [%0], %1;"
                             :: "r"(fullb), "r"((unsigned)STAGE_BYTES) : "memory");
                const unsigned At = smem_base + st * STAGE_BYTES;
                const unsigned Bt = At + A_BYTES;
                if (kt < 24) {
                    tma2d(At, (const void*)&mapX, kt * 32, rowBase, fullb);
                    tma2d(Bt, (const void*)&mapW, kt * 32, colBase, fullb);
                } else {
                    tma2d(At, (const void*)&mapAV, (kt - 24) * 32, rowBase, fullb);
                    tma2d(Bt, (const void*)&mapCV, (kt - 24) * 32, colBase, fullb);
                }
            }
        }
    } else if (warp == 1) {
        // ---------------- MMA issue role (lane 0 issues) ----------------
        for (int kt = 0; kt < TC_NKT; ++kt) {
            const int st = kt & 3;
            mbar_wait_par(smem_base + FULL_OFF + st * 8, (kt >> 2) & 1);
            if (lane == 0) {
                const uint64_t adesc = DESC_BASE |
                    (uint64_t)(((smem_base + st * STAGE_BYTES) >> 4) & 0x3FFF);
                const uint64_t bdesc = DESC_BASE |
                    (uint64_t)(((smem_base + st * STAGE_BYTES + A_BYTES) >> 4) & 0x3FFF);
#pragma unroll
                for (int step = 0; step < 4; ++step) {
                    const unsigned en = (kt > 0 || step > 0) ? 1u : 0u;
                    asm volatile(
                        "{\n\t.reg .pred p;\n\t"
                        "setp.ne.u32 p, %4, 0;\n\t"
                        "tcgen05.mma.cta_group::1.kind::tf32 [%0], %1, %2, %3, {%5, %5, %5, %5}, p;\n\t}"
                        :: "r"(tmem_base), "l"(adesc + step * 2), "l"(bdesc + step * 2),
                           "r"((unsigned)TC_IDESC), "r"(en), "r"(0u)
                        : "memory");
                }
                asm volatile(
                    "tcgen05.commit.cta_group::1.mbarrier::arrive::one.shared::cluster.b64 [%0];"
                    :: "r"(smem_base + EMPTY_OFF + st * 8) : "memory");
            }
        }
        if (lane == 0)
            asm volatile(
                "tcgen05.commit.cta_group::1.mbarrier::arrive::one.shared::cluster.b64 [%0];"
                :: "r"(smem_base + FIN_OFF) : "memory");
    }

    // ---------------- all threads: wait for final MMA completion ----------------
    mbar_wait_par(smem_base + FIN_OFF, 0);
    asm volatile("tcgen05.fence::after_thread_sync;" ::: "memory");

    const int sub = warp & 3;
    const int colBlk = (warp >> 2) * 128;
    const int row = rowBase + sub * 32 + lane;
#pragma unroll
    for (int chunk = 0; chunk < 4; ++chunk) {
        unsigned r[32];
        asm volatile(
            "tcgen05.ld.sync.aligned.32x32b.x32.b32 "
            "{%0, %1, %2, %3, %4, %5, %6, %7, %8, %9, %10, %11, %12, %13, %14, %15, "
            " %16, %17, %18, %19, %20, %21, %22, %23, %24, %25, %26, %27, %28, %29, %30, %31}, [%32];"
            : "=r"(r[0]), "=r"(r[1]), "=r"(r[2]), "=r"(r[3]), "=r"(r[4]), "=r"(r[5]),
              "=r"(r[6]), "=r"(r[7]), "=r"(r[8]), "=r"(r[9]), "=r"(r[10]), "=r"(r[11]),
              "=r"(r[12]), "=r"(r[13]), "=r"(r[14]), "=r"(r[15]), "=r"(r[16]), "=r"(r[17]),
              "=r"(r[18]), "=r"(r[19]), "=r"(r[20]), "=r"(r[21]), "=r"(r[22]), "=r"(r[23]),
              "=r"(r[24]), "=r"(r[25]), "=r"(r[26]), "=r"(r[27]), "=r"(r[28]), "=r"(r[29]),
              "=r"(r[30]), "=r"(r[31])
            : "r"(tmem_base + colBlk + chunk * 32));
        asm volatile("tcgen05.wait::ld.sync.aligned;" ::: "memory");
        const int c0 = colBase + colBlk + chunk * 32;
#pragma unroll
        for (int q = 0; q < 8; ++q) {
            const int cc = c0 + q * 4;
            float4 v;
            v.x = __uint_as_float(r[q * 4 + 0]) + __ldg(b + cc)     + __ldg(bc + cc);
            v.y = __uint_as_float(r[q * 4 + 1]) + __ldg(b + cc + 1) + __ldg(bc + cc + 1);
            v.z = __uint_as_float(r[q * 4 + 2]) + __ldg(b + cc + 2) + __ldg(bc + cc + 2);
            v.w = __uint_as_float(r[q * 4 + 3]) + __ldg(b + cc + 3) + __ldg(bc + cc + 3);
            *reinterpret_cast<float4*>(&g_h[(size_t)row * DOUT + cc]) = v;
        }
    }

    __syncthreads();
    if (warp == 0) {
        asm volatile("tcgen05.dealloc.cta_group::1.sync.aligned.b32 %0, %1;"
                     :: "r"(tmem_base), "r"(256u));
    }
#else
    // ==================== mma.sync fallback body ====================
    extern __shared__ float smf[];
    const int tid  = threadIdx.x;
    const int lane = tid & 31;
    const int warp = tid >> 5;
    const int wm = warp >> 2;            // 0..1 -> 64 rows
    const int wn = warp & 3;             // 0..3 -> 64 cols
    const int rowBase = blockIdx.y * TC_BM;
    const int colBase = blockIdx.x * TC_BN;
    const int r0 = lane >> 2;
    const int kq = lane & 3;

    float acc[4][8][4];
#pragma unroll
    for (int i = 0; i < 4; ++i)
#pragma unroll
        for (int j = 0; j < 8; ++j)
#pragma unroll
            for (int c = 0; c < 4; ++c) acc[i][j][c] = 0.f;

    auto load_tile = [&](int st, int kt) {
        float* As = smf + st * FB_STAGEF;
        float* Bs = As + 128 * FB_LDS;
        const bool mainseg = (kt < 24);
        const int kk = mainseg ? kt * 32 : (kt - 24) * 32;
        const float* aB = mainseg ? x : g_wav;
        const float* bB = mainseg ? W : g_wc_pad;
        const int aStride = mainseg ? DIN : NWP;
#pragma unroll
        for (int i = 0; i < 4; ++i) {
            const int idx = i * 256 + tid;
            const int row = idx >> 3, c = idx & 7;
            cp16(&As[row * FB_LDS + c * 4],
                 aB + (size_t)(rowBase + row) * aStride + kk + c * 4);
        }
#pragma unroll
        for (int i = 0; i < 8; ++i) {
            const int idx = i * 256 + tid;
            const int row = idx >> 3, c = idx & 7;
            cp16(&Bs[row * FB_LDS + c * 4],
                 bB + (size_t)(colBase + row) * aStride + kk + c * 4);
        }
    };

#pragma unroll
    for (int s = 0; s < 2; ++s) { load_tile(s, s); cp_commit(); }

    for (int kt = 0; kt < TC_NKT; ++kt) {
        cp_wait<1>();
        __syncthreads();
        const int st = kt & 1;
        const float* As = smf + st * FB_STAGEF;
        const float* Bs = As + 128 * FB_LDS;
#pragma unroll
        for (int ks = 0; ks < 4; ++ks) {
            const int ko = ks * 8;
            unsigned af[4][4];
            unsigned bf[8][2];
#pragma unroll
            for (int im = 0; im < 4; ++im) {
                const int m = wm * 64 + im * 16;
                af[im][0] = f2tf32(As[(m + r0) * FB_LDS + ko + kq]);
                af[im][1] = f2tf32(As[(m + r0 + 8) * FB_LDS + ko + kq]);
                af[im][2] = f2tf32(As[(m + r0) * FB_LDS + ko + kq + 4]);
                af[im][3] = f2tf32(As[(m + r0 + 8) * FB_LDS + ko + kq + 4]);
            }
#pragma unroll
            for (int in = 0; in < 8; ++in) {
                const int n = wn * 64 + in * 8;
                bf[in][0] = f2tf32(Bs[(n + r0) * FB_LDS + ko + kq]);
                bf[in][1] = f2tf32(Bs[(n + r0) * FB_LDS + ko + kq + 4]);
            }
#pragma unroll
            for (int im = 0; im < 4; ++im)
#pragma unroll
                for (int in = 0; in < 8; ++in)
                    mma_tf32(acc[im][in], af[im], bf[in]);
        }
        __syncthreads();
        if (kt + 2 < TC_NKT) load_tile(st, kt + 2);
        cp_commit();
    }

#pragma unroll
    for (int im = 0; im < 4; ++im) {
        const int r = rowBase + wm * 64 + im * 16 + r0;
#pragma unroll
        for (int in = 0; in < 8; ++in) {
            const int cc = colBase + wn * 64 + in * 8 + 2 * kq;
            const float b0 = __ldg(b + cc) + __ldg(bc + cc);
            const float b1 = __ldg(b + cc + 1) + __ldg(bc + cc + 1);
            float2 v;
            v.x = acc[im][in][0] + b0; v.y = acc[im][in][1] + b1;
            *reinterpret_cast<float2*>(&g_h[(size_t)r * DOUT + cc]) = v;
            v.x = acc[im][in][2] + b0; v.y = acc[im][in][3] + b1;
            *reinterpret_cast<float2*>(&g_h[(size_t)(r + 8) * DOUT + cc]) = v;
        }
    }
#endif
}

// ---------------------------------------------------------------------------
// Kernel 3: LayerNorm over DOUT=768, warp per row
// ---------------------------------------------------------------------------
__global__ __launch_bounds__(256) void k_ln(
    const float* __restrict__ gamma, const float* __restrict__ beta,
    float* __restrict__ out)
{
    const int lane = threadIdx.x & 31;
    const int warp = threadIdx.x >> 5;
    const int row = blockIdx.x * 8 + warp;

    const float4* hp = reinterpret_cast<const float4*>(g_h + (size_t)row * DOUT);
    float4 v[6];
    float s = 0.f, sq = 0.f;
#pragma unroll
    for (int i = 0; i < 6; ++i) {
        const float4 t = hp[i * 32 + lane];
        v[i] = t;
        s  += t.x + t.y + t.z + t.w;
        sq += t.x * t.x + t.y * t.y + t.z * t.z + t.w * t.w;
    }
#pragma unroll
    for (int off = 16; off > 0; off >>= 1) {
        s  += __shfl_xor_sync(0xffffffffu, s,  off);
        sq += __shfl_xor_sync(0xffffffffu, sq, off);
    }
    const float mean = s * (1.f / DOUT);
    const float var  = sq * (1.f / DOUT) - mean * mean;
    const float rstd = rsqrtf(var + LN_EPSF);

    float4* op = reinterpret_cast<float4*>(out + (size_t)row * DOUT);
    const float4* gp = reinterpret_cast<const float4*>(gamma);
    const float4* bp = reinterpret_cast<const float4*>(beta);
#pragma unroll
    for (int i = 0; i < 6; ++i) {
        const int idx = i * 32 + lane;
        const float4 g = __ldg(gp + idx);
        const float4 bt = __ldg(bp + idx);
        float4 o;
        o.x = (v[i].x - mean) * rstd * g.x + bt.x;
        o.y = (v[i].y - mean) * rstd * g.y + bt.y;
        o.z = (v[i].z - mean) * rstd * g.z + bt.z;
        o.w = (v[i].w - mean) * rstd * g.w + bt.w;
        op[idx] = o;
    }
}

// ---------------------------------------------------------------------------
typedef CUresult (*pfn_tmap_t)(
    CUtensorMap*, CUtensorMapDataType, cuuint32_t, void*,
    const cuuint64_t*, const cuuint64_t*, const cuuint32_t*, const cuuint32_t*,
    CUtensorMapInterleave, CUtensorMapSwizzle, CUtensorMapL2promotion,
    CUtensorMapFloatOOBfill);

static void make_map_2d(pfn_tmap_t enc, CUtensorMap* m, void* base,
                        uint64_t d0, uint64_t d1, uint64_t strideB,
                        uint32_t b0, uint32_t b1) {
    cuuint64_t dims[2]    = {d0, d1};
    cuuint64_t strides[1] = {strideB};
    cuuint32_t box[2]     = {b0, b1};
    cuuint32_t es[2]      = {1, 1};
    enc(m, CU_TENSOR_MAP_DATA_TYPE_FLOAT32, 2, base, dims, strides, box, es,
        CU_TENSOR_MAP_INTERLEAVE_NONE, CU_TENSOR_MAP_SWIZZLE_128B,
        CU_TENSOR_MAP_L2_PROMOTION_L2_128B, CU_TENSOR_MAP_FLOAT_OOB_FILL_NONE);
}

extern "C" void kernel_launch(void* const* d_in, const int* in_sizes, int n_in,
                              void* d_out, int out_size)
{
    const float* x     = (const float*)d_in[0];
    const float* W     = (const float*)d_in[1];
    const float* b     = (const float*)d_in[2];
    const float* Wp    = (const float*)d_in[3];
    const float* bp    = (const float*)d_in[4];
    const float* Wc    = (const float*)d_in[5];
    const float* bc    = (const float*)d_in[6];
    const float* scal  = (const float*)d_in[7];
    const float* trans = (const float*)d_in[8];
    const float* gamma = (const float*)d_in[9];
    const float* beta  = (const float*)d_in[10];
    float* out = (float*)d_out;

    cudaFuncSetAttribute(k_wavelet, cudaFuncAttributeMaxDynamicSharedMemorySize, WSMEM);
    cudaFuncSetAttribute(k_gemm_tc, cudaFuncAttributeMaxDynamicSharedMemorySize, TC_SMEM);

    // ---- build TMA tensormaps (host-side, capture-safe: no stream ops) ----
    void* encf = nullptr;
    cudaDriverEntryPointQueryResult qres;
    cudaGetDriverEntryPointByVersion("cuTensorMapEncodeTiled", &encf, 12000,
                                     cudaEnableDefault, &qres);
    pfn_tmap_t enc = (pfn_tmap_t)encf;

    void *pWav = nullptr, *pWc = nullptr;
    cudaGetSymbolAddress(&pWav, g_wav);
    cudaGetSymbolAddress(&pWc,  g_wc_pad);

    CUtensorMap mapX, mapW, mapAV, mapCV;
    make_map_2d(enc, &mapX,  (void*)x,   DIN, NROWS, (uint64_t)DIN * 4, 32, TC_BM);
    make_map_2d(enc, &mapW,  (void*)W,   DIN, DOUT,  (uint64_t)DIN * 4, 32, TC_BN);
    make_map_2d(enc, &mapAV, pWav,       NWP, NROWS, (uint64_t)NWP * 4, 32, TC_BM);
    make_map_2d(enc, &mapCV, pWc,        NWP, DOUT,  (uint64_t)NWP * 4, 32, TC_BN);

    k_split<<<(NW * DIN + 255) / 256, 256>>>(Wp);
    k_wcpad<<<(DOUT * NWP + 255) / 256, 256>>>(Wc);

    k_wavelet<<<NROWS / 128, 256, WSMEM>>>(x, bp, scal, trans);

    dim3 g2(DOUT / TC_BN, NROWS / TC_BM);   // (3, 256)
    k_gemm_tc<<<g2, 256, TC_SMEM>>>(mapX, mapW, mapAV, mapCV, x, W, b, bc);

    k_ln<<<NROWS / 8, 256>>>(gamma, beta, out);
}

// round 14
// speedup vs baseline: 3.6507x; 1.1798x over previous
#include <cuda_runtime.h>
#include <cuda.h>
#include <cstdint>
#include <math.h>

#define NROWS 32768
#define DIN   768
#define DOUT  768
#define NW    48
#define NH    16
#define NWP   64                 // padded wavelet width (stride of g_wav / g_wc_pad)
#define LN_EPSF 1e-5f

// ---------------- main GEMM tiling ----------------
#define TC_BM 128
#define TC_BN 256
#define TC_NKT 26                // K-tiles of 32 floats (768+64 = 832)
#define TC_STAGES 4
#define N_TILES 768              // 256 m-tiles x 3 n-tiles
#define GRID_P  148              // persistent CTAs
#define A_BYTES (128 * 128)      // 16 KB
#define B_BYTES (256 * 128)      // 32 KB
#define STAGE_BYTES (A_BYTES + B_BYTES)            // 48 KB
#define MBAR_OFF  (TC_STAGES * STAGE_BYTES)        // 196608
#define FULL_OFF  MBAR_OFF                         // 4 x 8
#define EMPTY_OFF (MBAR_OFF + 32)                  // 4 x 8
#define MDONE_OFF (MBAR_OFF + 64)                  // 2 x 8
#define EDONE_OFF (MBAR_OFF + 80)                  // 2 x 8
#define TMEMP_OFF (MBAR_OFF + 96)
#define BSUM_OFF  (MBAR_OFF + 112)                 // 768 floats (16B aligned)
#define TC_SMEM   (BSUM_OFF + 768 * 4)

// idesc: dtype=F32(1)@[4], atype=TF32(2)@[7], btype=TF32(2)@[10], N/8@[17], M/16@[24]
#define TC_IDESC ((1u << 4) | (2u << 7) | (2u << 10) | ((TC_BN / 8) << 17) | ((TC_BM / 16) << 24))

// SW128 K-major SMEM descriptor: LBO=1, SBO=64, version=1, layout=SW128(2)
#define DESC_BASE ((uint64_t(2) << 61) | (uint64_t(1) << 46) | (uint64_t(64) << 32) | (uint64_t(1) << 16))

// fallback (mma.sync) layout inside the same smem budget
#define FB_LDS 36
#define FB_STAGEF ((128 + 256) * FB_LDS)   // floats per stage

// ---------------- wavelet GEMM tiling (mma.sync 3xTF32) ----------------
#define LDSS 52
#define WSTAGES 2
#define NKTW 16
#define WSTAGEF ((128 + 96) * LDSS)
#define WSMEM   (WSTAGES * WSTAGEF * 4)   // 93184 bytes

// Scratch (allocation-free rule: static __device__ arrays)
__device__ float g_wav[(size_t)NROWS * NWP];
__device__ float g_h[(size_t)NROWS * DOUT];
__device__ float g_wp_hi[(size_t)NW * DIN];
__device__ float g_wp_lo[(size_t)NW * DIN];
__device__ float g_wc_pad[(size_t)DOUT * NWP];

// ---------------- helpers ----------------
__device__ __forceinline__ unsigned f2tf32(float f) {
    unsigned r;
    asm("cvt.rna.tf32.f32 %0, %1;" : "=r"(r) : "f"(f));
    return r;
}
__device__ __forceinline__ void tf32_split(float v, unsigned& hi, unsigned& lo) {
    hi = f2tf32(v);
    lo = f2tf32(v - __uint_as_float(hi));
}
__device__ __forceinline__ unsigned smem_u32(const void* p) {
    return (unsigned)__cvta_generic_to_shared(p);
}
__device__ __forceinline__ void cp16(void* smem_dst, const float* gmem_src) {
    asm volatile("cp.async.cg.shared.global [%0], [%1], 16;\n"
                 :: "r"(smem_u32(smem_dst)), "l"(gmem_src));
}
__device__ __forceinline__ void cp_commit() {
    asm volatile("cp.async.commit_group;\n");
}
template <int N>
__device__ __forceinline__ void cp_wait() {
    asm volatile("cp.async.wait_group %0;\n" :: "n"(N));
}
__device__ __forceinline__ void mma_tf32(float* c, const unsigned* a, const unsigned* b) {
    asm volatile(
        "mma.sync.aligned.m16n8k8.row.col.f32.tf32.tf32.f32 "
        "{%0,%1,%2,%3}, {%4,%5,%6,%7}, {%8,%9}, {%0,%1,%2,%3};"
        : "+f"(c[0]), "+f"(c[1]), "+f"(c[2]), "+f"(c[3])
        : "r"(a[0]), "r"(a[1]), "r"(a[2]), "r"(a[3]), "r"(b[0]), "r"(b[1]));
}
__device__ __forceinline__ void mbar_wait_par(unsigned mbar, unsigned parity) {
    asm volatile(
        "{\n\t.reg .pred P;\n\t"
        "W_%=: mbarrier.try_wait.parity.shared.b64 P, [%0], %1;\n\t"
        "@P bra D_%=;\n\t"
        "bra W_%=;\n\t"
        "D_%=:\n\t}"
        :: "r"(mbar), "r"(parity) : "memory");
}
__device__ __forceinline__ void tma2d(unsigned smem_dst, const void* map,
                                      int c0, int c1, unsigned mbar) {
    asm volatile(
        "cp.async.bulk.tensor.2d.shared::cta.global.tile.mbarrier::complete_tx::bytes "
        "[%0], [%1, {%2, %3}], [%4];"
        :: "r"(smem_dst), "l"(map), "r"(c0), "r"(c1), "r"(mbar) : "memory");
}

// ---------------------------------------------------------------------------
// Kernel 0a: pre-split Wp into tf32 hi/lo
// ---------------------------------------------------------------------------
__global__ void k_split(const float* __restrict__ Wp) {
    const int i = blockIdx.x * 256 + threadIdx.x;
    if (i < NW * DIN) {
        const float v = Wp[i];
        const float hi = __uint_as_float(f2tf32(v));
        g_wp_hi[i] = hi;
        g_wp_lo[i] = __uint_as_float(f2tf32(v - hi));
    }
}

// ---------------------------------------------------------------------------
// Kernel 0b: repack Wc [DOUT,48] -> g_wc_pad [DOUT,64] zero-padded
// ---------------------------------------------------------------------------
__global__ void k_wcpad(const float* __restrict__ Wc) {
    const int i = blockIdx.x * 256 + threadIdx.x;
    if (i < DOUT * NWP) {
        const int n = i >> 6, k = i & 63;
        g_wc_pad[i] = (k < NW) ? Wc[n * NW + k] : 0.f;
    }
}

// ---------------------------------------------------------------------------
// Kernel 1: wavelet path, 3xTF32 mma.sync GEMM; output stride 64, pad zeroed
// ---------------------------------------------------------------------------
__global__ __launch_bounds__(256, 2) void k_wavelet(
    const float* __restrict__ x,
    const float* __restrict__ bp, const float* __restrict__ scales,
    const float* __restrict__ trans)
{
    extern __shared__ float sm[];
    const int tid  = threadIdx.x;
    const int lane = tid & 31;
    const int warp = tid >> 5;
    const int rowBase = blockIdx.x * 128;
    const int r0 = lane >> 2;
    const int kq = lane & 3;

    float acc[6][4];
#pragma unroll
    for (int nt = 0; nt < 6; ++nt)
#pragma unroll
        for (int c = 0; c < 4; ++c) acc[nt][c] = 0.f;

    auto load_tile = [&](int st, int kt) {
        float* Xs = sm + st * WSTAGEF;
        float* Ws = Xs + 128 * LDSS;
#pragma unroll
        for (int i = 0; i < 6; ++i) {
            const int idx = i * 256 + tid;
            const int row = idx / 12, c4 = idx % 12;
            cp16(&Xs[row * LDSS + c4 * 4],
                 x + (size_t)(rowBase + row) * DIN + kt * 48 + c4 * 4);
        }
#pragma unroll
        for (int i = 0; i < 5; ++i) {
            const int idx = i * 256 + tid;
            if (idx < 1152) {
                const int row = idx / 12, c4 = idx % 12;
                const float* src = (row < 48)
                    ? g_wp_hi + (size_t)row * DIN + kt * 48 + c4 * 4
                    : g_wp_lo + (size_t)(row - 48) * DIN + kt * 48 + c4 * 4;
                cp16(&Ws[row * LDSS + c4 * 4], src);
            }
        }
    };

#pragma unroll
    for (int s = 0; s < WSTAGES; ++s) { load_tile(s, s); cp_commit(); }

    for (int kt = 0; kt < NKTW; ++kt) {
        cp_wait<WSTAGES - 1>();
        __syncthreads();
        const int st = kt % WSTAGES;
        const float* Xs = sm + st * WSTAGEF;
        const float* Ws = Xs + 128 * LDSS;
        const int m = warp * 16;
#pragma unroll
        for (int ks = 0; ks < 6; ++ks) {
            const int ko = ks * 8;
            unsigned ah[4], al[4];
            tf32_split(Xs[(m + r0) * LDSS + ko + kq],          ah[0], al[0]);
            tf32_split(Xs[(m + r0 + 8) * LDSS + ko + kq],      ah[1], al[1]);
            tf32_split(Xs[(m + r0) * LDSS + ko + kq + 4],      ah[2], al[2]);
            tf32_split(Xs[(m + r0 + 8) * LDSS + ko + kq + 4],  ah[3], al[3]);
#pragma unroll
            for (int nt = 0; nt < 6; ++nt) {
                unsigned bh[2], bl[2];
                bh[0] = __float_as_uint(Ws[(nt * 8 + r0) * LDSS + ko + kq]);
                bh[1] = __float_as_uint(Ws[(nt * 8 + r0) * LDSS + ko + kq + 4]);
                bl[0] = __float_as_uint(Ws[(48 + nt * 8 + r0) * LDSS + ko + kq]);
                bl[1] = __float_as_uint(Ws[(48 + nt * 8 + r0) * LDSS + ko + kq + 4]);
                mma_tf32(acc[nt], ah, bl);
                mma_tf32(acc[nt], al, bh);
                mma_tf32(acc[nt], ah, bh);
            }
        }
        __syncthreads();
        if (kt + WSTAGES < NKTW) load_tile(st, kt + WSTAGES);
        cp_commit();
    }

    // zero the pad columns 48..63 for this block's 128 rows
#pragma unroll
    for (int i = 0; i < 8; ++i) {
        const int idx = i * 256 + tid;          // 0..2047
        const int row = idx >> 4, col = 48 + (idx & 15);
        g_wav[(size_t)(rowBase + row) * NWP + col] = 0.f;
    }

    const int rA = rowBase + warp * 16 + r0;
#pragma unroll
    for (int nt = 0; nt < 6; ++nt) {
        const int j0 = nt * 8 + 2 * kq;
        const float bp0 = __ldg(bp + j0),     bp1 = __ldg(bp + j0 + 1);
        const float t0  = __ldg(trans + j0),  t1  = __ldg(trans + j0 + 1);
        const float sc0 = __ldg(scales + j0), sc1 = __ldg(scales + j0 + 1);
#pragma unroll
        for (int half = 0; half < 2; ++half) {
            const int r = rA + half * 8;
            const float s0 = (acc[nt][half * 2 + 0] + bp0 - t0) / sc0;
            const float s1 = (acc[nt][half * 2 + 1] + bp1 - t1) / sc1;
            float w0, w1;
            if (nt < 2) {               // haar
                w0 = (s0 >= 0.f && s0 < 0.5f) ? 1.f : ((s0 >= 0.5f && s0 < 1.f) ? -1.f : 0.f);
                w1 = (s1 >= 0.f && s1 < 0.5f) ? 1.f : ((s1 >= 0.5f && s1 < 1.f) ? -1.f : 0.f);
            } else if (nt < 4) {        // mexican hat
                w0 = (1.f - s0 * s0) * expf(-0.5f * s0 * s0);
                w1 = (1.f - s1 * s1) * expf(-0.5f * s1 * s1);
            } else {                    // morlet
                w0 = cosf(5.0f * s0) * expf(-0.5f * s0 * s0);
                w1 = cosf(5.0f * s1) * expf(-0.5f * s1 * s1);
            }
            float2 o;
            o.x = 0.5f * w0 * (1.f + erff(w0 * 0.7071067811865475f));
            o.y = 0.5f * w1 * (1.f + erff(w1 * 0.7071067811865475f));
            *reinterpret_cast<float2*>(&g_wav[(size_t)r * NWP + j0]) = o;
        }
    }
}

// ---------------------------------------------------------------------------
// Kernel 2: persistent tcgen05+TMA GEMM, double-buffered TMEM epilogue overlap
// ---------------------------------------------------------------------------
__global__ __launch_bounds__(256, 1) void k_gemm_tc(
    const __grid_constant__ CUtensorMap mapX,
    const __grid_constant__ CUtensorMap mapW,
    const __grid_constant__ CUtensorMap mapAV,
    const __grid_constant__ CUtensorMap mapCV,
    const float* __restrict__ x, const float* __restrict__ W,
    const float* __restrict__ b, const float* __restrict__ bc)
{
#if defined(__CUDA_ARCH__) && defined(__CUDA_ARCH_FEAT_SM103_ALL)
    // ==================== tcgen05 + TMA persistent body ====================
    extern __shared__ __align__(1024) char smc[];
    const unsigned smem_base = smem_u32(smc);
    const int tid  = threadIdx.x;
    const int lane = tid & 31;
    const int warp = tid >> 5;
    const int bid  = blockIdx.x;
    const int nt_local = (N_TILES - bid + GRID_P - 1) / GRID_P;   // 5 or 6

    if (warp == 0) {
        asm volatile("tcgen05.alloc.cta_group::1.sync.aligned.shared::cta.b32 [%0], %1;"
                     :: "r"(smem_base + TMEMP_OFF), "r"(512u) : "memory");
    }
    if (tid == 0) {
#pragma unroll
        for (int s = 0; s < TC_STAGES; ++s) {
            asm volatile("mbarrier.init.shared.b64 [%0], 1;"
                         :: "r"(smem_base + FULL_OFF + s * 8) : "memory");
            asm volatile("mbarrier.init.shared.b64 [%0], 1;"
                         :: "r"(smem_base + EMPTY_OFF + s * 8) : "memory");
        }
#pragma unroll
        for (int s = 0; s < 2; ++s) {
            asm volatile("mbarrier.init.shared.b64 [%0], 1;"
                         :: "r"(smem_base + MDONE_OFF + s * 8) : "memory");
            asm volatile("mbarrier.init.shared.b64 [%0], 4;"
                         :: "r"(smem_base + EDONE_OFF + s * 8) : "memory");
        }
    }
    // preload bias sums to smem (all threads)
    {
        float* bsum = (float*)(smc + BSUM_OFF);
        for (int i = tid; i < DOUT; i += 256) bsum[i] = b[i] + bc[i];
    }
    __syncthreads();
    unsigned tmem_base;
    asm volatile("ld.shared.b32 %0, [%1];" : "=r"(tmem_base) : "r"(smem_base + TMEMP_OFF));

    if (warp == 0) {
        // ---------------- TMA producer (continuous ring across tiles) -------
        int g = 0;
        for (int ti = 0; ti < nt_local; ++ti) {
            const int tile = bid + ti * GRID_P;
            const int rowB = (tile & 255) * TC_BM;
            const int colB = (tile >> 8) * TC_BN;
            for (int kt = 0; kt < TC_NKT; ++kt, ++g) {
                const int st = g & 3;
                mbar_wait_par(smem_base + EMPTY_OFF + st * 8, ((g >> 2) & 1) ^ 1);
                if (lane == 0) {
                    const unsigned fullb = smem_base + FULL_OFF + st * 8;
                    asm volatile("mbarrier.arrive.expect_tx.shared.b64 _, [%0], %1;"
                                 :: "r"(fullb), "r"((unsigned)STAGE_BYTES) : "memory");
                    const unsigned At = smem_base + st * STAGE_BYTES;
                    const unsigned Bt = At + A_BYTES;
                    if (kt < 24) {
                        tma2d(At, (const void*)&mapX, kt * 32, rowB, fullb);
                        tma2d(Bt, (const void*)&mapW, kt * 32, colB, fullb);
                    } else {
                        tma2d(At, (const void*)&mapAV, (kt - 24) * 32, rowB, fullb);
                        tma2d(Bt, (const void*)&mapCV, (kt - 24) * 32, colB, fullb);
                    }
                }
            }
        }
    } else if (warp == 1) {
        // ---------------- MMA issue role ----------------
        int g = 0;
        for (int ti = 0; ti < nt_local; ++ti) {
            const int buf = ti & 1;
            const unsigned dT = tmem_base + buf * 256;
            if (ti >= 2)   // wait epilogue of tile ti-2 (same buffer) done
                mbar_wait_par(smem_base + EDONE_OFF + buf * 8, ((ti >> 1) + 1) & 1);
            for (int kt = 0; kt < TC_NKT; ++kt, ++g) {
                const int st = g & 3;
                mbar_wait_par(smem_base + FULL_OFF + st * 8, (g >> 2) & 1);
                if (lane == 0) {
                    const uint64_t adesc = DESC_BASE |
                        (uint64_t)(((smem_base + st * STAGE_BYTES) >> 4) & 0x3FFF);
                    const uint64_t bdesc = DESC_BASE |
                        (uint64_t)(((smem_base + st * STAGE_BYTES + A_BYTES) >> 4) & 0x3FFF);
#pragma unroll
                    for (int step = 0; step < 4; ++step) {
                        const unsigned en = (kt > 0 || step > 0) ? 1u : 0u;
                        asm volatile(
                            "{\n\t.reg .pred p;\n\t"
                            "setp.ne.u32 p, %4, 0;\n\t"
                            "tcgen05.mma.cta_group::1.kind::tf32 [%0], %1, %2, %3, {%5, %5, %5, %5}, p;\n\t}"
                            :: "r"(dT), "l"(adesc + step * 2), "l"(bdesc + step * 2),
                               "r"((unsigned)TC_IDESC), "r"(en), "r"(0u)
                            : "memory");
                    }
                    asm volatile(
                        "tcgen05.commit.cta_group::1.mbarrier::arrive::one.shared::cluster.b64 [%0];"
                        :: "r"(smem_base + EMPTY_OFF + st * 8) : "memory");
                }
            }
            if (lane == 0)   // tile fully accumulated (tensor pipe is in-order)
                asm volatile(
                    "tcgen05.commit.cta_group::1.mbarrier::arrive::one.shared::cluster.b64 [%0];"
                    :: "r"(smem_base + MDONE_OFF + buf * 8) : "memory");
        }
    } else if (warp >= 2 && warp < 6) {
        // ---------------- epilogue role (4 warps = 4 TMEM subpartitions) ----
        const int sub = warp & 3;            // warps 2,3,4,5 -> subs 2,3,0,1
        const float* bsum = (const float*)(smc + BSUM_OFF);
        for (int ti = 0; ti < nt_local; ++ti) {
            const int buf = ti & 1;
            const unsigned dT = tmem_base + buf * 256;
            const int tile = bid + ti * GRID_P;
            const int rowB = (tile & 255) * TC_BM;
            const int colB = (tile >> 8) * TC_BN;
            mbar_wait_par(smem_base + MDONE_OFF + buf * 8, (ti >> 1) & 1);
            asm volatile("tcgen05.fence::after_thread_sync;" ::: "memory");
            const int row = rowB + sub * 32 + lane;
#pragma unroll
            for (int chunk = 0; chunk < 8; ++chunk) {
                unsigned r[32];
                asm volatile(
                    "tcgen05.ld.sync.aligned.32x32b.x32.b32 "
                    "{%0, %1, %2, %3, %4, %5, %6, %7, %8, %9, %10, %11, %12, %13, %14, %15, "
                    " %16, %17, %18, %19, %20, %21, %22, %23, %24, %25, %26, %27, %28, %29, %30, %31}, [%32];"
                    : "=r"(r[0]), "=r"(r[1]), "=r"(r[2]), "=r"(r[3]), "=r"(r[4]), "=r"(r[5]),
                      "=r"(r[6]), "=r"(r[7]), "=r"(r[8]), "=r"(r[9]), "=r"(r[10]), "=r"(r[11]),
                      "=r"(r[12]), "=r"(r[13]), "=r"(r[14]), "=r"(r[15]), "=r"(r[16]), "=r"(r[17]),
                      "=r"(r[18]), "=r"(r[19]), "=r"(r[20]), "=r"(r[21]), "=r"(r[22]), "=r"(r[23]),
                      "=r"(r[24]), "=r"(r[25]), "=r"(r[26]), "=r"(r[27]), "=r"(r[28]), "=r"(r[29]),
                      "=r"(r[30]), "=r"(r[31])
                    : "r"(dT + chunk * 32));
                asm volatile("tcgen05.wait::ld.sync.aligned;" ::: "memory");
                const int c0 = colB + chunk * 32;
                const int cl = chunk * 32;
#pragma unroll
                for (int q = 0; q < 8; ++q) {
                    const float4 bb = *reinterpret_cast<const float4*>(bsum + c0 + q * 4 - colB + colB);
                    float4 v;
                    v.x = __uint_as_float(r[q * 4 + 0]) + bsum[c0 + q * 4 + 0];
                    v.y = __uint_as_float(r[q * 4 + 1]) + bsum[c0 + q * 4 + 1];
                    v.z = __uint_as_float(r[q * 4 + 2]) + bsum[c0 + q * 4 + 2];
                    v.w = __uint_as_float(r[q * 4 + 3]) + bsum[c0 + q * 4 + 3];
                    (void)bb; (void)cl;
                    *reinterpret_cast<float4*>(&g_h[(size_t)row * DOUT + c0 + q * 4]) = v;
                }
            }
            __syncwarp();
            if (lane == 0)
                asm volatile("mbarrier.arrive.shared.b64 _, [%0];"
                             :: "r"(smem_base + EDONE_OFF + buf * 8) : "memory");
        }
    }
    // warps 6,7 idle through mainloop

    __syncthreads();
    if (warp == 0) {
        asm volatile("tcgen05.dealloc.cta_group::1.sync.aligned.b32 %0, %1;"
                     :: "r"(tmem_base), "r"(512u));
    }
#else
    // ==================== mma.sync fallback body (persistent) ====================
    extern __shared__ float smf[];
    const int tid  = threadIdx.x;
    const int lane = tid & 31;
    const int warp = tid >> 5;
    const int wm = warp >> 2;
    const int wn = warp & 3;
    const int r0 = lane >> 2;
    const int kq = lane & 3;

    for (int tile = blockIdx.x; tile < N_TILES; tile += GRID_P) {
        const int rowBase = (tile & 255) * TC_BM;
        const int colBase = (tile >> 8) * TC_BN;

        float acc[4][8][4];
#pragma unroll
        for (int i = 0; i < 4; ++i)
#pragma unroll
            for (int j = 0; j < 8; ++j)
#pragma unroll
                for (int c = 0; c < 4; ++c) acc[i][j][c] = 0.f;

        auto load_tile = [&](int st, int kt) {
            float* As = smf + st * FB_STAGEF;
            float* Bs = As + 128 * FB_LDS;
            const bool mainseg = (kt < 24);
            const int kk = mainseg ? kt * 32 : (kt - 24) * 32;
            const float* aB = mainseg ? x : g_wav;
            const float* bB = mainseg ? W : g_wc_pad;
            const int aStride = mainseg ? DIN : NWP;
#pragma unroll
            for (int i = 0; i < 4; ++i) {
                const int idx = i * 256 + tid;
                const int row = idx >> 3, c = idx & 7;
                cp16(&As[row * FB_LDS + c * 4],
                     aB + (size_t)(rowBase + row) * aStride + kk + c * 4);
            }
#pragma unroll
            for (int i = 0; i < 8; ++i) {
                const int idx = i * 256 + tid;
                const int row = idx >> 3, c = idx & 7;
                cp16(&Bs[row * FB_LDS + c * 4],
                     bB + (size_t)(colBase + row) * aStride + kk + c * 4);
            }
        };

#pragma unroll
        for (int s = 0; s < 2; ++s) { load_tile(s, s); cp_commit(); }

        for (int kt = 0; kt < TC_NKT; ++kt) {
            cp_wait<1>();
            __syncthreads();
            const int st = kt & 1;
            const float* As = smf + st * FB_STAGEF;
            const float* Bs = As + 128 * FB_LDS;
#pragma unroll
            for (int ks = 0; ks < 4; ++ks) {
                const int ko = ks * 8;
                unsigned af[4][4];
                unsigned bf[8][2];
#pragma unroll
                for (int im = 0; im < 4; ++im) {
                    const int m = wm * 64 + im * 16;
                    af[im][0] = f2tf32(As[(m + r0) * FB_LDS + ko + kq]);
                    af[im][1] = f2tf32(As[(m + r0 + 8) * FB_LDS + ko + kq]);
                    af[im][2] = f2tf32(As[(m + r0) * FB_LDS + ko + kq + 4]);
                    af[im][3] = f2tf32(As[(m + r0 + 8) * FB_LDS + ko + kq + 4]);
                }
#pragma unroll
                for (int in = 0; in < 8; ++in) {
                    const int n = wn * 64 + in * 8;
                    bf[in][0] = f2tf32(Bs[(n + r0) * FB_LDS + ko + kq]);
                    bf[in][1] = f2tf32(Bs[(n + r0) * FB_LDS + ko + kq + 4]);
                }
#pragma unroll
                for (int im = 0; im < 4; ++im)
#pragma unroll
                    for (int in = 0; in < 8; ++in)
                        mma_tf32(acc[im][in], af[im], bf[in]);
            }
            __syncthreads();
            if (kt + 2 < TC_NKT) load_tile(st, kt + 2);
            cp_commit();
        }

#pragma unroll
        for (int im = 0; im < 4; ++im) {
            const int r = rowBase + wm * 64 + im * 16 + r0;
#pragma unroll
            for (int in = 0; in < 8; ++in) {
                const int cc = colBase + wn * 64 + in * 8 + 2 * kq;
                const float b0 = __ldg(b + cc) + __ldg(bc + cc);
                const float b1 = __ldg(b + cc + 1) + __ldg(bc + cc + 1);
                float2 v;
                v.x = acc[im][in][0] + b0; v.y = acc[im][in][1] + b1;
                *reinterpret_cast<float2*>(&g_h[(size_t)r * DOUT + cc]) = v;
                v.x = acc[im][in][2] + b0; v.y = acc[im][in][3] + b1;
                *reinterpret_cast<float2*>(&g_h[(size_t)(r + 8) * DOUT + cc]) = v;
            }
        }
        __syncthreads();
    }
#endif
}

// ---------------------------------------------------------------------------
// Kernel 3: LayerNorm over DOUT=768, warp per row
// ---------------------------------------------------------------------------
__global__ __launch_bounds__(256) void k_ln(
    const float* __restrict__ gamma, const float* __restrict__ beta,
    float* __restrict__ out)
{
    const int lane = threadIdx.x & 31;
    const int warp = threadIdx.x >> 5;
    const int row = blockIdx.x * 8 + warp;

    const float4* hp = reinterpret_cast<const float4*>(g_h + (size_t)row * DOUT);
    float4 v[6];
    float s = 0.f, sq = 0.f;
#pragma unroll
    for (int i = 0; i < 6; ++i) {
        const float4 t = hp[i * 32 + lane];
        v[i] = t;
        s  += t.x + t.y + t.z + t.w;
        sq += t.x * t.x + t.y * t.y + t.z * t.z + t.w * t.w;
    }
#pragma unroll
    for (int off = 16; off > 0; off >>= 1) {
        s  += __shfl_xor_sync(0xffffffffu, s,  off);
        sq += __shfl_xor_sync(0xffffffffu, sq, off);
    }
    const float mean = s * (1.f / DOUT);
    const float var  = sq * (1.f / DOUT) - mean * mean;
    const float rstd = rsqrtf(var + LN_EPSF);

    float4* op = reinterpret_cast<float4*>(out + (size_t)row * DOUT);
    const float4* gp = reinterpret_cast<const float4*>(gamma);
    const float4* bp = reinterpret_cast<const float4*>(beta);
#pragma unroll
    for (int i = 0; i < 6; ++i) {
        const int idx = i * 32 + lane;
        const float4 g = __ldg(gp + idx);
        const float4 bt = __ldg(bp + idx);
        float4 o;
        o.x = (v[i].x - mean) * rstd * g.x + bt.x;
        o.y = (v[i].y - mean) * rstd * g.y + bt.y;
        o.z = (v[i].z - mean) * rstd * g.z + bt.z;
        o.w = (v[i].w - mean) * rstd * g.w + bt.w;
        op[idx] = o;
    }
}

// ---------------------------------------------------------------------------
typedef CUresult (*pfn_tmap_t)(
    CUtensorMap*, CUtensorMapDataType, cuuint32_t, void*,
    const cuuint64_t*, const cuuint64_t*, const cuuint32_t*, const cuuint32_t*,
    CUtensorMapInterleave, CUtensorMapSwizzle, CUtensorMapL2promotion,
    CUtensorMapFloatOOBfill);

static void make_map_2d(pfn_tmap_t enc, CUtensorMap* m, void* base,
                        uint64_t d0, uint64_t d1, uint64_t strideB,
                        uint32_t b0, uint32_t b1) {
    cuuint64_t dims[2]    = {d0, d1};
    cuuint64_t strides[1] = {strideB};
    cuuint32_t box[2]     = {b0, b1};
    cuuint32_t es[2]      = {1, 1};
    enc(m, CU_TENSOR_MAP_DATA_TYPE_FLOAT32, 2, base, dims, strides, box, es,
        CU_TENSOR_MAP_INTERLEAVE_NONE, CU_TENSOR_MAP_SWIZZLE_128B,
        CU_TENSOR_MAP_L2_PROMOTION_L2_128B, CU_TENSOR_MAP_FLOAT_OOB_FILL_NONE);
}

extern "C" void kernel_launch(void* const* d_in, const int* in_sizes, int n_in,
                              void* d_out, int out_size)
{
    const float* x     = (const float*)d_in[0];
    const float* W     = (const float*)d_in[1];
    const float* b     = (const float*)d_in[2];
    const float* Wp    = (const float*)d_in[3];
    const float* bp    = (const float*)d_in[4];
    const float* Wc    = (const float*)d_in[5];
    const float* bc    = (const float*)d_in[6];
    const float* scal  = (const float*)d_in[7];
    const float* trans = (const float*)d_in[8];
    const float* gamma = (const float*)d_in[9];
    const float* beta  = (const float*)d_in[10];
    float* out = (float*)d_out;

    cudaFuncSetAttribute(k_wavelet, cudaFuncAttributeMaxDynamicSharedMemorySize, WSMEM);
    cudaFuncSetAttribute(k_gemm_tc, cudaFuncAttributeMaxDynamicSharedMemorySize, TC_SMEM);

    // ---- build TMA tensormaps (host-side, capture-safe: no stream ops) ----
    void* encf = nullptr;
    cudaDriverEntryPointQueryResult qres;
    cudaGetDriverEntryPointByVersion("cuTensorMapEncodeTiled", &encf, 12000,
                                     cudaEnableDefault, &qres);
    pfn_tmap_t enc = (pfn_tmap_t)encf;

    void *pWav = nullptr, *pWc = nullptr;
    cudaGetSymbolAddress(&pWav, g_wav);
    cudaGetSymbolAddress(&pWc,  g_wc_pad);

    CUtensorMap mapX, mapW, mapAV, mapCV;
    make_map_2d(enc, &mapX,  (void*)x,   DIN, NROWS, (uint64_t)DIN * 4, 32, TC_BM);
    make_map_2d(enc, &mapW,  (void*)W,   DIN, DOUT,  (uint64_t)DIN * 4, 32, TC_BN);
    make_map_2d(enc, &mapAV, pWav,       NWP, NROWS, (uint64_t)NWP * 4, 32, TC_BM);
    make_map_2d(enc, &mapCV, pWc,        NWP, DOUT,  (uint64_t)NWP * 4, 32, TC_BN);

    k_split<<<(NW * DIN + 255) / 256, 256>>>(Wp);
    k_wcpad<<<(DOUT * NWP + 255) / 256, 256>>>(Wc);

    k_wavelet<<<NROWS / 128, 256, WSMEM>>>(x, bp, scal, trans);

    k_gemm_tc<<<GRID_P, 256, TC_SMEM>>>(mapX, mapW, mapAV, mapCV, x, W, b, bc);

    k_ln<<<NROWS / 8, 256>>>(gamma, beta, out);
}

// round 15
// speedup vs baseline: 3.8893x; 1.0654x over previous
#include <cuda_runtime.h>
#include <cuda.h>
#include <cstdint>
#include <math.h>

#define NROWS 32768
#define DIN   768
#define DOUT  768
#define NW    48
#define NH    16
#define NWP   64
#define LN_EPSF 1e-5f

// ---------------- main GEMM tiling (cg2: 256x256 tiles) ----------------
#define TC_BM 256                // per cluster
#define TC_BN 256
#define TC_NKT 26                // K-tiles of 32 floats (768+64 = 832)
#define TC_STAGES 4
#define N_TILES2 384             // 128 m2-tiles x 3 n-tiles
#define N_CLUST 74
#define GRID_P  148
#define A_BYTES 16384            // 128 rows x 128 B (per CTA half)
#define B_BYTES 16384            // 128 rows x 128 B (per CTA half)
#define STAGE_BYTES (A_BYTES + B_BYTES)            // 32 KB per CTA
#define MBAR_OFF  (TC_STAGES * STAGE_BYTES)        // 131072
#define FULL_OFF  MBAR_OFF
#define EMPTY_OFF (MBAR_OFF + 32)
#define MDONE_OFF (MBAR_OFF + 64)
#define EDONE_OFF (MBAR_OFF + 80)
#define TMEMP_OFF (MBAR_OFF + 96)
#define BSUM_OFF  (MBAR_OFF + 112)
#define TC_SMEM   (BSUM_OFF + 768 * 4)

// cg2 idesc: dtype=F32(1)@[4], atype=TF32(2)@[7], btype=TF32(2)@[10], N/8@[17], M/16@[24]
#define TC_IDESC ((1u << 4) | (2u << 7) | (2u << 10) | ((TC_BN / 8) << 17) | ((TC_BM / 16) << 24))

// SW128 K-major SMEM descriptor: LBO=1, SBO=64, version=1, layout=SW128(2)
#define DESC_BASE ((uint64_t(2) << 61) | (uint64_t(1) << 46) | (uint64_t(64) << 32) | (uint64_t(1) << 16))

// fallback (mma.sync) layout
#define FB_LDS 36
#define FB_STAGEF ((128 + 256) * FB_LDS)
#define N_TILES_FB 768

// ---------------- wavelet GEMM tiling (mma.sync 3xTF32) ----------------
#define LDSS 52
#define WSTAGES 2
#define NKTW 16
#define WSTAGEF ((128 + 96) * LDSS)
#define WSMEM   (WSTAGES * WSTAGEF * 4)

// Scratch
__device__ float g_wav[(size_t)NROWS * NWP];
__device__ float g_h[(size_t)NROWS * DOUT];
__device__ float g_wp_hi[(size_t)NW * DIN];
__device__ float g_wp_lo[(size_t)NW * DIN];
__device__ float g_wc_pad[(size_t)DOUT * NWP];

// ---------------- helpers ----------------
__device__ __forceinline__ unsigned f2tf32(float f) {
    unsigned r;
    asm("cvt.rna.tf32.f32 %0, %1;" : "=r"(r) : "f"(f));
    return r;
}
__device__ __forceinline__ void tf32_split(float v, unsigned& hi, unsigned& lo) {
    hi = f2tf32(v);
    lo = f2tf32(v - __uint_as_float(hi));
}
__device__ __forceinline__ unsigned smem_u32(const void* p) {
    return (unsigned)__cvta_generic_to_shared(p);
}
__device__ __forceinline__ void cp16(void* smem_dst, const float* gmem_src) {
    asm volatile("cp.async.cg.shared.global [%0], [%1], 16;\n"
                 :: "r"(smem_u32(smem_dst)), "l"(gmem_src));
}
__device__ __forceinline__ void cp_commit() {
    asm volatile("cp.async.commit_group;\n");
}
template <int N>
__device__ __forceinline__ void cp_wait() {
    asm volatile("cp.async.wait_group %0;\n" :: "n"(N));
}
__device__ __forceinline__ void mma_tf32(float* c, const unsigned* a, const unsigned* b) {
    asm volatile(
        "mma.sync.aligned.m16n8k8.row.col.f32.tf32.tf32.f32 "
        "{%0,%1,%2,%3}, {%4,%5,%6,%7}, {%8,%9}, {%0,%1,%2,%3};"
        : "+f"(c[0]), "+f"(c[1]), "+f"(c[2]), "+f"(c[3])
        : "r"(a[0]), "r"(a[1]), "r"(a[2]), "r"(a[3]), "r"(b[0]), "r"(b[1]));
}
__device__ __forceinline__ void mbar_wait_par(unsigned mbar, unsigned parity) {
    asm volatile(
        "{\n\t.reg .pred P;\n\t"
        "W_%=: mbarrier.try_wait.parity.shared.b64 P, [%0], %1;\n\t"
        "@P bra D_%=;\n\t"
        "bra W_%=;\n\t"
        "D_%=:\n\t}"
        :: "r"(mbar), "r"(parity) : "memory");
}
// cg2 TMA: both CTAs load own smem; completion tx -> leader (bit-24 cleared) barrier
__device__ __forceinline__ void tma3d_cg2(unsigned smem_dst, const void* map,
                                          int c0, int c1, unsigned mbar) {
    asm volatile(
        "{\n\t.reg .b32 lb;\n\t"
        "and.b32 lb, %5, 0xFEFFFFFF;\n\t"
        "cp.async.bulk.tensor.3d.cta_group::2.shared::cluster.global"
        ".tile.mbarrier::complete_tx::bytes [%0], [%1, {%2, %3, %4}], [lb];\n\t}"
        :: "r"(smem_dst), "l"(map), "r"(c0), "r"(c1), "r"(0), "r"(mbar) : "memory");
}

// ---------------------------------------------------------------------------
__global__ void k_split(const float* __restrict__ Wp) {
    const int i = blockIdx.x * 256 + threadIdx.x;
    if (i < NW * DIN) {
        const float v = Wp[i];
        const float hi = __uint_as_float(f2tf32(v));
        g_wp_hi[i] = hi;
        g_wp_lo[i] = __uint_as_float(f2tf32(v - hi));
    }
}

__global__ void k_wcpad(const float* __restrict__ Wc) {
    const int i = blockIdx.x * 256 + threadIdx.x;
    if (i < DOUT * NWP) {
        const int n = i >> 6, k = i & 63;
        g_wc_pad[i] = (k < NW) ? Wc[n * NW + k] : 0.f;
    }
}

// ---------------------------------------------------------------------------
// Kernel 1: wavelet path, 3xTF32 mma.sync GEMM; output stride 64, pad zeroed
// ---------------------------------------------------------------------------
__global__ __launch_bounds__(256, 2) void k_wavelet(
    const float* __restrict__ x,
    const float* __restrict__ bp, const float* __restrict__ scales,
    const float* __restrict__ trans)
{
    extern __shared__ float sm[];
    const int tid  = threadIdx.x;
    const int lane = tid & 31;
    const int warp = tid >> 5;
    const int rowBase = blockIdx.x * 128;
    const int r0 = lane >> 2;
    const int kq = lane & 3;

    float acc[6][4];
#pragma unroll
    for (int nt = 0; nt < 6; ++nt)
#pragma unroll
        for (int c = 0; c < 4; ++c) acc[nt][c] = 0.f;

    auto load_tile = [&](int st, int kt) {
        float* Xs = sm + st * WSTAGEF;
        float* Ws = Xs + 128 * LDSS;
#pragma unroll
        for (int i = 0; i < 6; ++i) {
            const int idx = i * 256 + tid;
            const int row = idx / 12, c4 = idx % 12;
            cp16(&Xs[row * LDSS + c4 * 4],
                 x + (size_t)(rowBase + row) * DIN + kt * 48 + c4 * 4);
        }
#pragma unroll
        for (int i = 0; i < 5; ++i) {
            const int idx = i * 256 + tid;
            if (idx < 1152) {
                const int row = idx / 12, c4 = idx % 12;
                const float* src = (row < 48)
                    ? g_wp_hi + (size_t)row * DIN + kt * 48 + c4 * 4
                    : g_wp_lo + (size_t)(row - 48) * DIN + kt * 48 + c4 * 4;
                cp16(&Ws[row * LDSS + c4 * 4], src);
            }
        }
    };

#pragma unroll
    for (int s = 0; s < WSTAGES; ++s) { load_tile(s, s); cp_commit(); }

    for (int kt = 0; kt < NKTW; ++kt) {
        cp_wait<WSTAGES - 1>();
        __syncthreads();
        const int st = kt % WSTAGES;
        const float* Xs = sm + st * WSTAGEF;
        const float* Ws = Xs + 128 * LDSS;
        const int m = warp * 16;
#pragma unroll
        for (int ks = 0; ks < 6; ++ks) {
            const int ko = ks * 8;
            unsigned ah[4], al[4];
            tf32_split(Xs[(m + r0) * LDSS + ko + kq],          ah[0], al[0]);
            tf32_split(Xs[(m + r0 + 8) * LDSS + ko + kq],      ah[1], al[1]);
            tf32_split(Xs[(m + r0) * LDSS + ko + kq + 4],      ah[2], al[2]);
            tf32_split(Xs[(m + r0 + 8) * LDSS + ko + kq + 4],  ah[3], al[3]);
#pragma unroll
            for (int nt = 0; nt < 6; ++nt) {
                unsigned bh[2], bl[2];
                bh[0] = __float_as_uint(Ws[(nt * 8 + r0) * LDSS + ko + kq]);
                bh[1] = __float_as_uint(Ws[(nt * 8 + r0) * LDSS + ko + kq + 4]);
                bl[0] = __float_as_uint(Ws[(48 + nt * 8 + r0) * LDSS + ko + kq]);
                bl[1] = __float_as_uint(Ws[(48 + nt * 8 + r0) * LDSS + ko + kq + 4]);
                mma_tf32(acc[nt], ah, bl);
                mma_tf32(acc[nt], al, bh);
                mma_tf32(acc[nt], ah, bh);
            }
        }
        __syncthreads();
        if (kt + WSTAGES < NKTW) load_tile(st, kt + WSTAGES);
        cp_commit();
    }

#pragma unroll
    for (int i = 0; i < 8; ++i) {
        const int idx = i * 256 + tid;
        const int row = idx >> 4, col = 48 + (idx & 15);
        g_wav[(size_t)(rowBase + row) * NWP + col] = 0.f;
    }

    const int rA = rowBase + warp * 16 + r0;
#pragma unroll
    for (int nt = 0; nt < 6; ++nt) {
        const int j0 = nt * 8 + 2 * kq;
        const float bp0 = __ldg(bp + j0),     bp1 = __ldg(bp + j0 + 1);
        const float t0  = __ldg(trans + j0),  t1  = __ldg(trans + j0 + 1);
        const float sc0 = __ldg(scales + j0), sc1 = __ldg(scales + j0 + 1);
#pragma unroll
        for (int half = 0; half < 2; ++half) {
            const int r = rA + half * 8;
            const float s0 = (acc[nt][half * 2 + 0] + bp0 - t0) / sc0;
            const float s1 = (acc[nt][half * 2 + 1] + bp1 - t1) / sc1;
            float w0, w1;
            if (nt < 2) {
                w0 = (s0 >= 0.f && s0 < 0.5f) ? 1.f : ((s0 >= 0.5f && s0 < 1.f) ? -1.f : 0.f);
                w1 = (s1 >= 0.f && s1 < 0.5f) ? 1.f : ((s1 >= 0.5f && s1 < 1.f) ? -1.f : 0.f);
            } else if (nt < 4) {
                w0 = (1.f - s0 * s0) * expf(-0.5f * s0 * s0);
                w1 = (1.f - s1 * s1) * expf(-0.5f * s1 * s1);
            } else {
                w0 = cosf(5.0f * s0) * expf(-0.5f * s0 * s0);
                w1 = cosf(5.0f * s1) * expf(-0.5f * s1 * s1);
            }
            float2 o;
            o.x = 0.5f * w0 * (1.f + erff(w0 * 0.7071067811865475f));
            o.y = 0.5f * w1 * (1.f + erff(w1 * 0.7071067811865475f));
            *reinterpret_cast<float2*>(&g_wav[(size_t)r * NWP + j0]) = o;
        }
    }
}

// ---------------------------------------------------------------------------
// Kernel 2: persistent cg2 tcgen05+TMA GEMM (256x256 cluster tiles)
// ---------------------------------------------------------------------------
__global__ __launch_bounds__(256, 1) __cluster_dims__(2, 1, 1) void k_gemm_tc(
    const __grid_constant__ CUtensorMap mapX,
    const __grid_constant__ CUtensorMap mapW,
    const __grid_constant__ CUtensorMap mapAV,
    const __grid_constant__ CUtensorMap mapCV,
    const float* __restrict__ x, const float* __restrict__ W,
    const float* __restrict__ b, const float* __restrict__ bc)
{
#if defined(__CUDA_ARCH__) && defined(__CUDA_ARCH_FEAT_SM103_ALL)
    extern __shared__ __align__(1024) char smc[];
    const unsigned smem_base = smem_u32(smc);
    const int tid  = threadIdx.x;
    const int lane = tid & 31;
    const int warp = tid >> 5;
    unsigned rank;
    asm("mov.u32 %0, %%cluster_ctarank;" : "=r"(rank));
    const int cl = blockIdx.x >> 1;
    const int nt_local = (N_TILES2 - cl + N_CLUST - 1) / N_CLUST;   // 5 or 6

    if (warp == 0) {
        asm volatile("tcgen05.alloc.cta_group::2.sync.aligned.shared::cta.b32 [%0], %1;"
                     :: "r"(smem_base + TMEMP_OFF), "r"(512u) : "memory");
    }
    if (tid == 0) {
#pragma unroll
        for (int s = 0; s < TC_STAGES; ++s) {
            asm volatile("mbarrier.init.shared.b64 [%0], 1;"
                         :: "r"(smem_base + FULL_OFF + s * 8) : "memory");
            asm volatile("mbarrier.init.shared.b64 [%0], 1;"
                         :: "r"(smem_base + EMPTY_OFF + s * 8) : "memory");
        }
#pragma unroll
        for (int s = 0; s < 2; ++s) {
            asm volatile("mbarrier.init.shared.b64 [%0], 1;"
                         :: "r"(smem_base + MDONE_OFF + s * 8) : "memory");
            asm volatile("mbarrier.init.shared.b64 [%0], 8;"
                         :: "r"(smem_base + EDONE_OFF + s * 8) : "memory");
        }
    }
    {
        float* bsum = (float*)(smc + BSUM_OFF);
        for (int i = tid; i < DOUT; i += 256) bsum[i] = b[i] + bc[i];
    }
    __syncthreads();
    // cluster-wide: barriers + TMEM visible before peer-targeted TMA/commit
    asm volatile("barrier.cluster.arrive.aligned;" ::: "memory");
    asm volatile("barrier.cluster.wait.aligned;" ::: "memory");

    unsigned tmem_base;
    asm volatile("ld.shared.b32 %0, [%1];" : "=r"(tmem_base) : "r"(smem_base + TMEMP_OFF));

    if (warp == 0) {
        // ------- TMA producer (both CTAs; completions -> leader full[s]) ----
        int g = 0;
        for (int ti = 0; ti < nt_local; ++ti) {
            const int tile = cl + ti * N_CLUST;
            const int m2 = tile / 3, n = tile % 3;
            const int rowA = m2 * TC_BM + (int)rank * 128;
            const int rowB = n * TC_BN + (int)rank * 128;
            for (int kt = 0; kt < TC_NKT; ++kt, ++g) {
                const int st = g & 3;
                mbar_wait_par(smem_base + EMPTY_OFF + st * 8, ((g >> 2) & 1) ^ 1);
                if (lane == 0) {
                    const unsigned fullb = smem_base + FULL_OFF + st * 8;
                    if (rank == 0)      // leader expects both CTAs' bytes
                        asm volatile("mbarrier.arrive.expect_tx.shared.b64 _, [%0], %1;"
                                     :: "r"(fullb), "r"((unsigned)(2 * STAGE_BYTES)) : "memory");
                    const unsigned At = smem_base + st * STAGE_BYTES;
                    const unsigned Bt = At + A_BYTES;
                    if (kt < 24) {
                        tma3d_cg2(At, (const void*)&mapX, kt * 32, rowA, fullb);
                        tma3d_cg2(Bt, (const void*)&mapW, kt * 32, rowB, fullb);
                    } else {
                        tma3d_cg2(At, (const void*)&mapAV, (kt - 24) * 32, rowA, fullb);
                        tma3d_cg2(Bt, (const void*)&mapCV, (kt - 24) * 32, rowB, fullb);
                    }
                }
            }
        }
    } else if (warp == 1 && rank == 0) {
        // ------- MMA issue role (leader CTA only) ----
        int g = 0;
        for (int ti = 0; ti < nt_local; ++ti) {
            const int buf = ti & 1;
            const unsigned dT = tmem_base + buf * 256;
            if (ti >= 2)
                mbar_wait_par(smem_base + EDONE_OFF + buf * 8, ((ti >> 1) + 1) & 1);
            for (int kt = 0; kt < TC_NKT; ++kt, ++g) {
                const int st = g & 3;
                mbar_wait_par(smem_base + FULL_OFF + st * 8, (g >> 2) & 1);
                if (lane == 0) {
                    const uint64_t adesc = DESC_BASE |
                        (uint64_t)(((smem_base + st * STAGE_BYTES) >> 4) & 0x3FFF);
                    const uint64_t bdesc = DESC_BASE |
                        (uint64_t)(((smem_base + st * STAGE_BYTES + A_BYTES) >> 4) & 0x3FFF);
#pragma unroll
                    for (int step = 0; step < 4; ++step) {
                        const unsigned en = (kt > 0 || step > 0) ? 1u : 0u;
                        asm volatile(
                            "{\n\t.reg .pred p;\n\t"
                            "setp.ne.u32 p, %4, 0;\n\t"
                            "tcgen05.mma.cta_group::2.kind::tf32 [%0], %1, %2, %3, "
                            "{%5, %5, %5, %5, %5, %5, %5, %5}, p;\n\t}"
                            :: "r"(dT), "l"(adesc + step * 2), "l"(bdesc + step * 2),
                               "r"((unsigned)TC_IDESC), "r"(en), "r"(0u)
                            : "memory");
                    }
                    // release stage in BOTH CTAs
                    asm volatile(
                        "tcgen05.commit.cta_group::2.mbarrier::arrive::one.shared::cluster"
                        ".multicast::cluster.b64 [%0], %1;"
                        :: "r"(smem_base + EMPTY_OFF + st * 8), "h"((uint16_t)0x3) : "memory");
                }
            }
            if (lane == 0)  // tile accumulated -> both CTAs' mdone[buf]
                asm volatile(
                    "tcgen05.commit.cta_group::2.mbarrier::arrive::one.shared::cluster"
                    ".multicast::cluster.b64 [%0], %1;"
                    :: "r"(smem_base + MDONE_OFF + buf * 8), "h"((uint16_t)0x3) : "memory");
        }
    } else if (warp >= 2 && warp < 6) {
        // ------- epilogue role (4 warps/CTA; each CTA owns its 128 rows) ----
        const int sub = warp & 3;
        const float* bsum = (const float*)(smc + BSUM_OFF);
        for (int ti = 0; ti < nt_local; ++ti) {
            const int buf = ti & 1;
            const unsigned dT = tmem_base + buf * 256;
            const int tile = cl + ti * N_CLUST;
            const int m2 = tile / 3, n = tile % 3;
            const int colB = n * TC_BN;
            mbar_wait_par(smem_base + MDONE_OFF + buf * 8, (ti >> 1) & 1);
            asm volatile("tcgen05.fence::after_thread_sync;" ::: "memory");
            const int row = m2 * TC_BM + (int)rank * 128 + sub * 32 + lane;
#pragma unroll
            for (int chunk = 0; chunk < 8; ++chunk) {
                unsigned r[32];
                asm volatile(
                    "tcgen05.ld.sync.aligned.32x32b.x32.b32 "
                    "{%0, %1, %2, %3, %4, %5, %6, %7, %8, %9, %10, %11, %12, %13, %14, %15, "
                    " %16, %17, %18, %19, %20, %21, %22, %23, %24, %25, %26, %27, %28, %29, %30, %31}, [%32];"
                    : "=r"(r[0]), "=r"(r[1]), "=r"(r[2]), "=r"(r[3]), "=r"(r[4]), "=r"(r[5]),
                      "=r"(r[6]), "=r"(r[7]), "=r"(r[8]), "=r"(r[9]), "=r"(r[10]), "=r"(r[11]),
                      "=r"(r[12]), "=r"(r[13]), "=r"(r[14]), "=r"(r[15]), "=r"(r[16]), "=r"(r[17]),
                      "=r"(r[18]), "=r"(r[19]), "=r"(r[20]), "=r"(r[21]), "=r"(r[22]), "=r"(r[23]),
                      "=r"(r[24]), "=r"(r[25]), "=r"(r[26]), "=r"(r[27]), "=r"(r[28]), "=r"(r[29]),
                      "=r"(r[30]), "=r"(r[31])
                    : "r"(dT + chunk * 32));
                asm volatile("tcgen05.wait::ld.sync.aligned;" ::: "memory");
                const int c0 = colB + chunk * 32;
#pragma unroll
                for (int q = 0; q < 8; ++q) {
                    float4 v;
                    v.x = __uint_as_float(r[q * 4 + 0]) + bsum[c0 + q * 4 + 0];
                    v.y = __uint_as_float(r[q * 4 + 1]) + bsum[c0 + q * 4 + 1];
                    v.z = __uint_as_float(r[q * 4 + 2]) + bsum[c0 + q * 4 + 2];
                    v.w = __uint_as_float(r[q * 4 + 3]) + bsum[c0 + q * 4 + 3];
                    *reinterpret_cast<float4*>(&g_h[(size_t)row * DOUT + c0 + q * 4]) = v;
                }
            }
            __syncwarp();
            if (lane == 0) {  // arrive leader's edone[buf] (cross-CTA)
                asm volatile(
                    "{\n\t.reg .b32 la;\n\t"
                    "and.b32 la, %0, 0xFEFFFFFF;\n\t"
                    "mbarrier.arrive.shared::cluster.b64 _, [la];\n\t}"
                    :: "r"(smem_base + EDONE_OFF + buf * 8) : "memory");
            }
        }
    }

    __syncthreads();
    if (warp == 0) {
        asm volatile("tcgen05.relinquish_alloc_permit.cta_group::2.sync.aligned;");
        asm volatile("tcgen05.dealloc.cta_group::2.sync.aligned.b32 %0, %1;"
                     :: "r"(tmem_base), "r"(512u));
    }
    asm volatile("barrier.cluster.arrive.aligned;" ::: "memory");
    asm volatile("barrier.cluster.wait.aligned;" ::: "memory");
#else
    // ==================== mma.sync fallback body (persistent) ====================
    extern __shared__ float smf[];
    const int tid  = threadIdx.x;
    const int lane = tid & 31;
    const int warp = tid >> 5;
    const int wm = warp >> 2;
    const int wn = warp & 3;
    const int r0 = lane >> 2;
    const int kq = lane & 3;

    for (int tile = blockIdx.x; tile < N_TILES_FB; tile += GRID_P) {
        const int rowBase = (tile & 255) * 128;
        const int colBase = (tile >> 8) * 256;

        float acc[4][8][4];
#pragma unroll
        for (int i = 0; i < 4; ++i)
#pragma unroll
            for (int j = 0; j < 8; ++j)
#pragma unroll
                for (int c = 0; c < 4; ++c) acc[i][j][c] = 0.f;

        auto load_tile = [&](int st, int kt) {
            float* As = smf + st * FB_STAGEF;
            float* Bs = As + 128 * FB_LDS;
            const bool mainseg = (kt < 24);
            const int kk = mainseg ? kt * 32 : (kt - 24) * 32;
            const float* aB = mainseg ? x : g_wav;
            const float* bB = mainseg ? W : g_wc_pad;
            const int aStride = mainseg ? DIN : NWP;
#pragma unroll
            for (int i = 0; i < 4; ++i) {
                const int idx = i * 256 + tid;
                const int row = idx >> 3, c = idx & 7;
                cp16(&As[row * FB_LDS + c * 4],
                     aB + (size_t)(rowBase + row) * aStride + kk + c * 4);
            }
#pragma unroll
            for (int i = 0; i < 8; ++i) {
                const int idx = i * 256 + tid;
                const int row = idx >> 3, c = idx & 7;
                cp16(&Bs[row * FB_LDS + c * 4],
                     bB + (size_t)(colBase + row) * aStride + kk + c * 4);
            }
        };

#pragma unroll
        for (int s = 0; s < 2; ++s) { load_tile(s, s); cp_commit(); }

        for (int kt = 0; kt < TC_NKT; ++kt) {
            cp_wait<1>();
            __syncthreads();
            const int st = kt & 1;
            const float* As = smf + st * FB_STAGEF;
            const float* Bs = As + 128 * FB_LDS;
#pragma unroll
            for (int ks = 0; ks < 4; ++ks) {
                const int ko = ks * 8;
                unsigned af[4][4];
                unsigned bf[8][2];
#pragma unroll
                for (int im = 0; im < 4; ++im) {
                    const int m = wm * 64 + im * 16;
                    af[im][0] = f2tf32(As[(m + r0) * FB_LDS + ko + kq]);
                    af[im][1] = f2tf32(As[(m + r0 + 8) * FB_LDS + ko + kq]);
                    af[im][2] = f2tf32(As[(m + r0) * FB_LDS + ko + kq + 4]);
                    af[im][3] = f2tf32(As[(m + r0 + 8) * FB_LDS + ko + kq + 4]);
                }
#pragma unroll
                for (int in = 0; in < 8; ++in) {
                    const int n = wn * 64 + in * 8;
                    bf[in][0] = f2tf32(Bs[(n + r0) * FB_LDS + ko + kq]);
                    bf[in][1] = f2tf32(Bs[(n + r0) * FB_LDS + ko + kq + 4]);
                }
#pragma unroll
                for (int im = 0; im < 4; ++im)
#pragma unroll
                    for (int in = 0; in < 8; ++in)
                        mma_tf32(acc[im][in], af[im], bf[in]);
            }
            __syncthreads();
            if (kt + 2 < TC_NKT) load_tile(st, kt + 2);
            cp_commit();
        }

#pragma unroll
        for (int im = 0; im < 4; ++im) {
            const int r = rowBase + wm * 64 + im * 16 + r0;
#pragma unroll
            for (int in = 0; in < 8; ++in) {
                const int cc = colBase + wn * 64 + in * 8 + 2 * kq;
                const float b0 = __ldg(b + cc) + __ldg(bc + cc);
                const float b1 = __ldg(b + cc + 1) + __ldg(bc + cc + 1);
                float2 v;
                v.x = acc[im][in][0] + b0; v.y = acc[im][in][1] + b1;
                *reinterpret_cast<float2*>(&g_h[(size_t)r * DOUT + cc]) = v;
                v.x = acc[im][in][2] + b0; v.y = acc[im][in][3] + b1;
                *reinterpret_cast<float2*>(&g_h[(size_t)(r + 8) * DOUT + cc]) = v;
            }
        }
        __syncthreads();
    }
#endif
}

// ---------------------------------------------------------------------------
// Kernel 3: LayerNorm over DOUT=768, warp per row
// ---------------------------------------------------------------------------
__global__ __launch_bounds__(256) void k_ln(
    const float* __restrict__ gamma, const float* __restrict__ beta,
    float* __restrict__ out)
{
    const int lane = threadIdx.x & 31;
    const int warp = threadIdx.x >> 5;
    const int row = blockIdx.x * 8 + warp;

    const float4* hp = reinterpret_cast<const float4*>(g_h + (size_t)row * DOUT);
    float4 v[6];
    float s = 0.f, sq = 0.f;
#pragma unroll
    for (int i = 0; i < 6; ++i) {
        const float4 t = hp[i * 32 + lane];
        v[i] = t;
        s  += t.x + t.y + t.z + t.w;
        sq += t.x * t.x + t.y * t.y + t.z * t.z + t.w * t.w;
    }
#pragma unroll
    for (int off = 16; off > 0; off >>= 1) {
        s  += __shfl_xor_sync(0xffffffffu, s,  off);
        sq += __shfl_xor_sync(0xffffffffu, sq, off);
    }
    const float mean = s * (1.f / DOUT);
    const float var  = sq * (1.f / DOUT) - mean * mean;
    const float rstd = rsqrtf(var + LN_EPSF);

    float4* op = reinterpret_cast<float4*>(out + (size_t)row * DOUT);
    const float4* gp = reinterpret_cast<const float4*>(gamma);
    const float4* bp = reinterpret_cast<const float4*>(beta);
#pragma unroll
    for (int i = 0; i < 6; ++i) {
        const int idx = i * 32 + lane;
        const float4 g = __ldg(gp + idx);
        const float4 bt = __ldg(bp + idx);
        float4 o;
        o.x = (v[i].x - mean) * rstd * g.x + bt.x;
        o.y = (v[i].y - mean) * rstd * g.y + bt.y;
        o.z = (v[i].z - mean) * rstd * g.z + bt.z;
        o.w = (v[i].w - mean) * rstd * g.w + bt.w;
        op[idx] = o;
    }
}

// ---------------------------------------------------------------------------
typedef CUresult (*pfn_tmap_t)(
    CUtensorMap*, CUtensorMapDataType, cuuint32_t, void*,
    const cuuint64_t*, const cuuint64_t*, const cuuint32_t*, const cuuint32_t*,
    CUtensorMapInterleave, CUtensorMapSwizzle, CUtensorMapL2promotion,
    CUtensorMapFloatOOBfill);

static void make_map_3d(pfn_tmap_t enc, CUtensorMap* m, void* base,
                        uint64_t d0, uint64_t d1, uint64_t strideB,
                        uint32_t b0, uint32_t b1) {
    cuuint64_t dims[3]    = {d0, d1, 1};
    cuuint64_t strides[2] = {strideB, d1 * strideB};
    cuuint32_t box[3]     = {b0, b1, 1};
    cuuint32_t es[3]      = {1, 1, 1};
    enc(m, CU_TENSOR_MAP_DATA_TYPE_FLOAT32, 3, base, dims, strides, box, es,
        CU_TENSOR_MAP_INTERLEAVE_NONE, CU_TENSOR_MAP_SWIZZLE_128B,
        CU_TENSOR_MAP_L2_PROMOTION_L2_128B, CU_TENSOR_MAP_FLOAT_OOB_FILL_NONE);
}

extern "C" void kernel_launch(void* const* d_in, const int* in_sizes, int n_in,
                              void* d_out, int out_size)
{
    const float* x     = (const float*)d_in[0];
    const float* W     = (const float*)d_in[1];
    const float* b     = (const float*)d_in[2];
    const float* Wp    = (const float*)d_in[3];
    const float* bp    = (const float*)d_in[4];
    const float* Wc    = (const float*)d_in[5];
    const float* bc    = (const float*)d_in[6];
    const float* scal  = (const float*)d_in[7];
    const float* trans = (const float*)d_in[8];
    const float* gamma = (const float*)d_in[9];
    const float* beta  = (const float*)d_in[10];
    float* out = (float*)d_out;

    cudaFuncSetAttribute(k_wavelet, cudaFuncAttributeMaxDynamicSharedMemorySize, WSMEM);
    cudaFuncSetAttribute(k_gemm_tc, cudaFuncAttributeMaxDynamicSharedMemorySize, TC_SMEM);

    void* encf = nullptr;
    cudaDriverEntryPointQueryResult qres;
    cudaGetDriverEntryPointByVersion("cuTensorMapEncodeTiled", &encf, 12000,
                                     cudaEnableDefault, &qres);
    pfn_tmap_t enc = (pfn_tmap_t)encf;

    void *pWav = nullptr, *pWc = nullptr;
    cudaGetSymbolAddress(&pWav, g_wav);
    cudaGetSymbolAddress(&pWc,  g_wc_pad);

    // boxes: 32 K-floats x 128 rows (per-CTA halves)
    CUtensorMap mapX, mapW, mapAV, mapCV;
    make_map_3d(enc, &mapX,  (void*)x,   DIN, NROWS, (uint64_t)DIN * 4, 32, 128);
    make_map_3d(enc, &mapW,  (void*)W,   DIN, DOUT,  (uint64_t)DIN * 4, 32, 128);
    make_map_3d(enc, &mapAV, pWav,       NWP, NROWS, (uint64_t)NWP * 4, 32, 128);
    make_map_3d(enc, &mapCV, pWc,        NWP, DOUT,  (uint64_t)NWP * 4, 32, 128);

    k_split<<<(NW * DIN + 255) / 256, 256>>>(Wp);
    k_wcpad<<<(DOUT * NWP + 255) / 256, 256>>>(Wc);

    k_wavelet<<<NROWS / 128, 256, WSMEM>>>(x, bp, scal, trans);

    k_gemm_tc<<<GRID_P, 256, TC_SMEM>>>(mapX, mapW, mapAV, mapCV, x, W, b, bc);

    k_ln<<<NROWS / 8, 256>>>(gamma, beta, out);
}